// round 12
// baseline (speedup 1.0000x reference)
#include <cuda_runtime.h>
#include <cuda_bf16.h>
#include <math.h>
#include <stdint.h>

#define Bn   8
#define Cc   256
#define C2   512
#define Hh   128
#define Ww   128
#define HW   16384
#define BHW  131072
#define HID  64

// Scratch (device globals: allocation-free rule)
__device__ float g_off[(size_t)BHW * 4];
__device__ float g_wfrag[C2 / 8 * 512];       // p1 weights in tf32 mma B-fragment order
__device__ float g_p2eff[HID * 4];
__device__ float g_p2beff[4];
__device__ float g_pooled[Bn * C2];
__device__ float g_mod[Bn * Cc];

// ---- cp.async helpers ----
__device__ __forceinline__ uint32_t smem_u32(const void* p) {
    return (uint32_t)__cvta_generic_to_shared(p);
}
__device__ __forceinline__ void cpa4(uint32_t dst, const float* src, int sz) {
    asm volatile("cp.async.ca.shared.global [%0], [%1], 4, %2;" :: "r"(dst), "l"(src), "r"(sz));
}
__device__ __forceinline__ void cpa16(uint32_t dst, const float* src, int sz) {
    asm volatile("cp.async.ca.shared.global [%0], [%1], 16, %2;" :: "r"(dst), "l"(src), "r"(sz));
}
__device__ __forceinline__ void cpa_commit() { asm volatile("cp.async.commit_group;"); }
__device__ __forceinline__ void cpa_wait2() { asm volatile("cp.async.wait_group 2;"); }
__device__ __forceinline__ void cpa_wait1() { asm volatile("cp.async.wait_group 1;"); }
__device__ __forceinline__ void cpa_wait0() { asm volatile("cp.async.wait_group 0;"); }

// ---- tf32 mma ----
#define MMA_TF32(D, A, B0, B1) \
    asm volatile("mma.sync.aligned.m16n8k8.row.col.f32.tf32.tf32.f32 " \
        "{%0,%1,%2,%3}, {%4,%5,%6,%7}, {%8,%9}, {%0,%1,%2,%3};" \
        : "+f"((D)[0]), "+f"((D)[1]), "+f"((D)[2]), "+f"((D)[3]) \
        : "r"((A)[0]), "r"((A)[1]), "r"((A)[2]), "r"((A)[3]), "r"(B0), "r"(B1))

// ---------------- prep: pack p1 weights into mma B-fragment order, fold p2 ----------------
__global__ void prep_kernel(const float* __restrict__ p1w,
                            const float* __restrict__ p2w,
                            const float* __restrict__ p2b) {
    int idx = blockIdx.x * 256 + threadIdx.x;
    if (idx < 64 * 512) {
        int chunk = idx >> 9, rem = idx & 511;
        int q = rem >> 7, lrem = rem & 127;
        int ll = lrem >> 2, jj = lrem & 3;
        int j = q * 4 + jj, t = j >> 1, r = j & 1;
        int n = t * 8 + (ll >> 2);
        int k = chunk * 8 + (ll & 3) + r * 4;
        float v = p1w[n * 512 + k];
        uint32_t tf;
        asm("cvt.rna.tf32.f32 %0, %1;" : "=r"(tf) : "f"(v));
        g_wfrag[idx] = __uint_as_float(tf);
    }
    if (blockIdx.x == 0) {
        const float SC = 0.1f * 0.5f * 127.0f * 0.25f;
        if (threadIdx.x < HID) {
            int h = threadIdx.x;
            g_p2eff[h*4+0] = SC*(p2w[0*HID+h]+p2w[2*HID+h]+p2w[4*HID+h]+p2w[6*HID+h]);
            g_p2eff[h*4+1] = SC*(p2w[1*HID+h]+p2w[3*HID+h]+p2w[5*HID+h]+p2w[7*HID+h]);
            g_p2eff[h*4+2] = SC*(p2w[8*HID+h]+p2w[10*HID+h]+p2w[12*HID+h]+p2w[14*HID+h]);
            g_p2eff[h*4+3] = SC*(p2w[9*HID+h]+p2w[11*HID+h]+p2w[13*HID+h]+p2w[15*HID+h]);
        } else if (threadIdx.x < HID + 4) {
            int j = threadIdx.x - HID;
            int base = (j >> 1) * 8 + (j & 1);  // 0,1,8,9
            g_p2beff[j] = SC*(p2b[base]+p2b[base+2]+p2b[base+4]+p2b[base+6]);
        }
    }
}

// ---------------- GAP ----------------
__global__ void gap_kernel(const float* __restrict__ rgb, const float* __restrict__ tir) {
    int bc = blockIdx.x;               // 0..4095
    int b = bc >> 9, c2 = bc & 511;
    const float* src = (c2 < Cc) ? rgb + (size_t)(b * Cc + c2) * HW
                                 : tir + (size_t)(b * Cc + c2 - Cc) * HW;
    float s = 0.f;
    for (int i = threadIdx.x; i < HW; i += 256) s += src[i];
    __shared__ float sm[8];
    #pragma unroll
    for (int o = 16; o; o >>= 1) s += __shfl_xor_sync(0xffffffffu, s, o);
    if ((threadIdx.x & 31) == 0) sm[threadIdx.x >> 5] = s;
    __syncthreads();
    if (threadIdx.x < 8) {
        float v = sm[threadIdx.x];
        #pragma unroll
        for (int o = 4; o; o >>= 1) v += __shfl_xor_sync(0xffu, v, o);
        if (threadIdx.x == 0) g_pooled[bc] = v * (1.0f / (float)HW);
    }
}

// ---------------- modulation ----------------
__global__ void mod_kernel(const float* __restrict__ m1w, const float* __restrict__ m1b,
                           const float* __restrict__ m2w, const float* __restrict__ m2b) {
    int b = blockIdx.x;
    __shared__ float hid[HID];
    __shared__ float pl[C2];
    for (int i = threadIdx.x; i < C2; i += 256) pl[i] = g_pooled[b * C2 + i];
    __syncthreads();
    if (threadIdx.x < HID) {
        float s = m1b[threadIdx.x];
        const float* wr = m1w + threadIdx.x * C2;
        for (int c = 0; c < C2; c++) s = fmaf(wr[c], pl[c], s);
        hid[threadIdx.x] = fmaxf(s, 0.f);
    }
    __syncthreads();
    int o = threadIdx.x;
    float s = m2b[o];
    const float* wr = m2w + o * HID;
    #pragma unroll
    for (int h = 0; h < HID; h++) s = fmaf(wr[h], hid[h], s);
    g_mod[b * Cc + o] = 1.f / (1.f + expf(-s));
}

// ---------------- FUSED: depthwise 3x3 + tf32 tensor-core p1 GEMM + folded p2 ----------------
// Tile 16x8 = 128 px, 8 warps, 3 CTAs/SM. Warp w = pixels [16w,16w+16) = one m16 tile
// x 8 n-tiles (d[32]). StageB thread = 1px x 4ch. Swizzled XS: phys ch = ch ^ (px&4).
#define TW 16
#define TH 8
#define NPX (TW * TH)      // 128
#define ROWF 24            // floats per halo row (16B aligned, [tx0-4, tx0+20))
#define CHT  240           // 10 * 24
#define TILEF (8 * CHT)    // 1920 floats per chunk buffer
#define CHK 8
#define NCHUNK (C2 / CHK)
#define NCP 480            // 16B granules per chunk (8ch * 10r * 6)

// dynamic smem layout (floats)
#define OFF_TILES 0                        // [4][1920]
#define OFF_XS    (OFF_TILES + 4*TILEF)    // [2][1024]
#define OFF_WB    (OFF_XS + 2*1024)        // [4][512]
#define OFF_WDW   (OFF_WB + 4*512)         // [512*12]
#define SMEM_FLOATS (OFF_WDW + C2*12)
#define SMEM_BYTES  (SMEM_FLOATS * 4)

__global__ __launch_bounds__(256, 3)
void dwgemm_kernel(const float* __restrict__ rgb, const float* __restrict__ tir,
                   const float* __restrict__ dww, const float* __restrict__ dwb,
                   const float* __restrict__ p1b) {
    extern __shared__ __align__(16) float sm[];
    float* TILES = sm + OFF_TILES;
    float* XS    = sm + OFF_XS;
    float* WB    = sm + OFF_WB;
    float* WDW   = sm + OFF_WDW;

    const int tid = threadIdx.x;
    const int tx0 = blockIdx.x * TW;
    const int ty0 = blockIdx.y * TH;
    const int b   = blockIdx.z;
    const int w = tid >> 5;    // warp id
    const int l = tid & 31;    // lane

    // ---- chunk-invariant loader addressing (16B granules, 480 total) ----
    int ofs[2], doff[2];
    unsigned vmask = 0;
    #pragma unroll
    for (int sl = 0; sl < 2; sl++) {
        int i = sl * 256 + tid;
        bool have = (i < NCP);
        int ii = have ? i : 0;
        int ch = ii / 60, rem = ii - ch * 60;
        int r = rem / 6, ci = rem - r * 6;
        int gy = ty0 + r - 1;
        int gx0 = tx0 - 4 + ci * 4;
        bool in = have && (gy >= 0) && (gy < Hh) && (gx0 >= 0) && (gx0 <= Ww - 4);
        ofs[sl]  = in ? (ch * HW + gy * Ww + gx0) : 0;
        doff[sl] = (ch * CHT + r * ROWF + ci * 4) * 4;
        if (in) vmask |= 1u << sl;
    }

    const float* rbase = rgb + (size_t)b * Cc * HW;
    const float* tbase = tir + (size_t)b * Cc * HW;
    const uint32_t tiles_a = smem_u32(TILES);
    const uint32_t wb_a    = smem_u32(WB);
    const uint32_t wdw_a   = smem_u32(WDW);

    auto load_chunk = [&](int chunk, int bt) {
        const float* base = (chunk < 32 ? rbase : tbase) + (size_t)((chunk & 31) * CHK) * HW;
        uint32_t dst0 = tiles_a + bt * (TILEF * 4);
        {
            int in = vmask & 1;
            cpa16(dst0 + doff[0], base + ofs[0], in ? 16 : 0);
        }
        if (tid < NCP - 256) {
            int in = (vmask >> 1) & 1;
            cpa16(dst0 + doff[1], base + ofs[1], in ? 16 : 0);
        }
        if (tid < 128)
            cpa16(wb_a + (bt * 512 + tid * 4) * 4, g_wfrag + chunk * 512 + tid * 4, 16);
    };

    // stage B: thread = 1 pixel x 4 channels -> one swizzled float4 store
    auto stageB = [&](int chunk, int bt, int xb) {
        const int px = tid & 127, half = tid >> 7;
        const int lxB = px & 15, lyB = px >> 4;
        const float* t0 = TILES + bt * TILEF + (half * 4) * CHT + lyB * ROWF + lxB + 3;
        const float* wd = WDW + chunk * (CHK * 12) + (half * 4) * 12;
        float x[4];
        #pragma unroll
        for (int cc = 0; cc < 4; cc++) {
            const float* t = t0 + cc * CHT;
            float4 wa = *(const float4*)(wd + cc * 12);
            float4 wb = *(const float4*)(wd + cc * 12 + 4);
            float2 wc = *(const float2*)(wd + cc * 12 + 8);
            float o = wc.y;   // bias
            o = fmaf(wa.x, t[0],       fmaf(wa.y, t[1],       fmaf(wa.z, t[2],
                fmaf(wa.w, t[ROWF],    fmaf(wb.x, t[ROWF+1],  fmaf(wb.y, t[ROWF+2],
                fmaf(wb.z, t[2*ROWF],  fmaf(wb.w, t[2*ROWF+1],fmaf(wc.x, t[2*ROWF+2], o)))))))));
            x[cc] = o;
        }
        float* xp = XS + xb * 1024 + px * 8 + ((half * 4) ^ (px & 4));
        *(float4*)xp = make_float4(x[0], x[1], x[2], x[3]);
    };

    float d[32];
    #pragma unroll
    for (int i = 0; i < 32; i++) d[i] = 0.f;

    // prologue: dw taps (once) + chunks 0,1,2 in flight
    for (int i = tid; i < C2 * 12; i += 256) {
        int c2 = i / 12, k = i - c2 * 12;
        const float* src = (k < 9) ? dww + c2 * 9 + k : dwb + c2;
        cpa4(wdw_a + i * 4, src, (k <= 9) ? 4 : 0);
    }
    load_chunk(0, 0); cpa_commit();
    load_chunk(1, 1); cpa_commit();
    load_chunk(2, 2); cpa_commit();
    cpa_wait2();                 // taps + chunk 0 resident
    __syncthreads();
    stageB(0, 0, 0);

    for (int chunk = 0; chunk < NCHUNK; chunk++) {
        if (chunk + 2 < NCHUNK) cpa_wait1();
        else                    cpa_wait0();
        __syncthreads();

        if (chunk + 3 < NCHUNK) { load_chunk(chunk + 3, (chunk + 3) & 3); cpa_commit(); }
        if (chunk + 1 < NCHUNK) stageB(chunk + 1, (chunk + 1) & 3, (chunk + 1) & 1);

        // ---- stage C: tensor GEMM on XS[chunk&1] with WB[chunk&3] ----
        const float* xb = XS + (chunk & 1) * 1024;
        const float4* B4 = (const float4*)(WB + (chunk & 3) * 512);
        uint32_t a[4];
        const int c = l & 3;
        {
            int p0 = w * 16 + (l >> 2);
            int p1 = p0 + 8;
            int ad0 = p0 * 8 + (c ^ (p0 & 4));
            int ad1 = p1 * 8 + (c ^ (p1 & 4));
            a[0] = __float_as_uint(xb[ad0]);
            a[1] = __float_as_uint(xb[ad1]);
            a[2] = __float_as_uint(xb[ad0 ^ 4]);
            a[3] = __float_as_uint(xb[ad1 ^ 4]);
        }
        #pragma unroll
        for (int q = 0; q < 4; q++) {
            float4 B = B4[q * 32 + l];
            uint32_t b0a = __float_as_uint(B.x), b1a = __float_as_uint(B.y);
            uint32_t b0b = __float_as_uint(B.z), b1b = __float_as_uint(B.w);
            MMA_TF32(d + (2 * q) * 4,     a, b0a, b1a);
            MMA_TF32(d + (2 * q + 1) * 4, a, b0b, b1b);
        }
    }

    // ---- Epilogue: bias + ReLU + folded p2, quad-reduce over hid lanes ----
    float4 oA = make_float4(0.f, 0.f, 0.f, 0.f);
    float4 oB = make_float4(0.f, 0.f, 0.f, 0.f);
    const float4* P2 = (const float4*)g_p2eff;
    #pragma unroll
    for (int t = 0; t < 8; t++) {
        int h0 = t * 8 + (l & 3) * 2;
        float4 e0 = P2[h0], e1 = P2[h0 + 1];
        float bb0 = p1b[h0], bb1 = p1b[h0 + 1];
        const float* dd = d + t * 4;
        float r0 = fmaxf(dd[0] + bb0, 0.f), r1 = fmaxf(dd[1] + bb1, 0.f);
        float r2 = fmaxf(dd[2] + bb0, 0.f), r3 = fmaxf(dd[3] + bb1, 0.f);
        oA.x += e0.x * r0 + e1.x * r1;  oA.y += e0.y * r0 + e1.y * r1;
        oA.z += e0.z * r0 + e1.z * r1;  oA.w += e0.w * r0 + e1.w * r1;
        oB.x += e0.x * r2 + e1.x * r3;  oB.y += e0.y * r2 + e1.y * r3;
        oB.z += e0.z * r2 + e1.z * r3;  oB.w += e0.w * r2 + e1.w * r3;
    }
    #pragma unroll
    for (int o = 1; o <= 2; o <<= 1) {
        oA.x += __shfl_xor_sync(0xffffffffu, oA.x, o);
        oA.y += __shfl_xor_sync(0xffffffffu, oA.y, o);
        oA.z += __shfl_xor_sync(0xffffffffu, oA.z, o);
        oA.w += __shfl_xor_sync(0xffffffffu, oA.w, o);
        oB.x += __shfl_xor_sync(0xffffffffu, oB.x, o);
        oB.y += __shfl_xor_sync(0xffffffffu, oB.y, o);
        oB.z += __shfl_xor_sync(0xffffffffu, oB.z, o);
        oB.w += __shfl_xor_sync(0xffffffffu, oB.w, o);
    }
    if ((l & 3) == 0) {
        float4 bo = make_float4(g_p2beff[0], g_p2beff[1], g_p2beff[2], g_p2beff[3]);
        int p0 = w * 16 + (l >> 2);          // tile pixel
        int p1 = p0 + 8;
        int py0 = ty0 + (p0 >> 4), px0 = tx0 + (p0 & 15);
        int py1 = ty0 + (p1 >> 4), px1 = tx0 + (p1 & 15);
        float4 sA = make_float4(oA.x + bo.x, oA.y + bo.y, oA.z + bo.z, oA.w + bo.w);
        float4 sB = make_float4(oB.x + bo.x, oB.y + bo.y, oB.z + bo.z, oB.w + bo.w);
        ((float4*)g_off)[(size_t)b * HW + py0 * Ww + px0] = sA;
        ((float4*)g_off)[(size_t)b * HW + py1 * Ww + px1] = sB;
    }
}

// ---------------- bilinear sample + mod + quality ----------------
__global__ void sample_kernel(const float* __restrict__ rgb, const float* __restrict__ tir,
                              float* __restrict__ out) {
    int x = threadIdx.x;        // 128
    int y = blockIdx.x;         // 128
    int b = blockIdx.y;         // 8
    __shared__ float smod[Cc];
    for (int i = threadIdx.x; i < Cc; i += 128) smod[i] = g_mod[b * Cc + i];
    __syncthreads();
    int hw = y * Ww + x;
    int p = b * HW + hw;
    float4 off = ((const float4*)g_off)[p];

    float ixr = fminf(fmaxf((float)x + off.x, 0.f), 127.f);
    float iyr = fminf(fmaxf((float)y + off.y, 0.f), 127.f);
    float ixt = fminf(fmaxf((float)x + off.z, 0.f), 127.f);
    float iyt = fminf(fmaxf((float)y + off.w, 0.f), 127.f);

    float fx0r = floorf(ixr), fy0r = floorf(iyr);
    int x0r = (int)fx0r, y0r = (int)fy0r;
    int x1r = min(x0r + 1, 127), y1r = min(y0r + 1, 127);
    float wxr = ixr - fx0r, wyr = iyr - fy0r;
    int i00r = y0r*Ww + x0r, i01r = y0r*Ww + x1r, i10r = y1r*Ww + x0r, i11r = y1r*Ww + x1r;

    float fx0t = floorf(ixt), fy0t = floorf(iyt);
    int x0t = (int)fx0t, y0t = (int)fy0t;
    int x1t = min(x0t + 1, 127), y1t = min(y0t + 1, 127);
    float wxt = ixt - fx0t, wyt = iyt - fy0t;
    int i00t = y0t*Ww + x0t, i01t = y0t*Ww + x1t, i10t = y1t*Ww + x0t, i11t = y1t*Ww + x1t;

    const float* rb = rgb + (size_t)b * Cc * HW;
    const float* tb = tir + (size_t)b * Cc * HW;
    float* outR = out + (size_t)b * Cc * HW + hw;
    float* outT = out + (size_t)Bn * Cc * HW + (size_t)b * Cc * HW + hw;

    float qacc = 0.f;
    #pragma unroll 4
    for (int c = 0; c < Cc; c++) {
        size_t co = (size_t)c * HW;
        float v00 = rb[co + i00r], v01 = rb[co + i01r];
        float v10 = rb[co + i10r], v11 = rb[co + i11r];
        float topr = v00 * (1.f - wxr) + v01 * wxr;
        float botr = v10 * (1.f - wxr) + v11 * wxr;
        float rv = (topr * (1.f - wyr) + botr * wyr) * smod[c];

        float u00 = tb[co + i00t], u01 = tb[co + i01t];
        float u10 = tb[co + i10t], u11 = tb[co + i11t];
        float topt = u00 * (1.f - wxt) + u01 * wxt;
        float bott = u10 * (1.f - wxt) + u11 * wxt;
        float tv = (topt * (1.f - wyt) + bott * wyt) * smod[c];

        outR[co] = rv;
        outT[co] = tv;
        qacc += fabsf(rv - tv);
    }
    float q = 1.f - qacc * (1.f / (float)Cc);
    out[(size_t)2 * Bn * Cc * HW + p] = 1.f / (1.f + expf(-q));
}

extern "C" void kernel_launch(void* const* d_in, const int* in_sizes, int n_in,
                              void* d_out, int out_size) {
    const float* rgb  = (const float*)d_in[0];
    const float* tir  = (const float*)d_in[1];
    const float* dw_w = (const float*)d_in[2];
    const float* dw_b = (const float*)d_in[3];
    const float* p1_w = (const float*)d_in[4];
    const float* p1_b = (const float*)d_in[5];
    const float* p2_w = (const float*)d_in[6];
    const float* p2_b = (const float*)d_in[7];
    const float* m1_w = (const float*)d_in[8];
    const float* m1_b = (const float*)d_in[9];
    const float* m2_w = (const float*)d_in[10];
    const float* m2_b = (const float*)d_in[11];
    float* out = (float*)d_out;

    cudaFuncSetAttribute(dwgemm_kernel, cudaFuncAttributeMaxDynamicSharedMemorySize, SMEM_BYTES);

    prep_kernel<<<129, 256>>>(p1_w, p2_w, p2_b);
    gap_kernel<<<Bn * C2, 256>>>(rgb, tir);
    mod_kernel<<<Bn, 256>>>(m1_w, m1_b, m2_w, m2_b);
    dwgemm_kernel<<<dim3(Ww / TW, Hh / TH, Bn), 256, SMEM_BYTES>>>(rgb, tir, dw_w, dw_b, p1_b);
    sample_kernel<<<dim3(Hh, Bn), Ww>>>(rgb, tir, out);
}

// round 13
// speedup vs baseline: 1.2336x; 1.2336x over previous
#include <cuda_runtime.h>
#include <cuda_bf16.h>
#include <math.h>
#include <stdint.h>

#define Bn   8
#define Cc   256
#define C2   512
#define Hh   128
#define Ww   128
#define HW   16384
#define BHW  131072
#define HID  64

// Scratch (device globals: allocation-free rule)
__device__ float g_off[(size_t)BHW * 4];
__device__ float g_wfrag[C2 / 8 * 512];       // p1 weights in tf32 mma B-fragment order
__device__ float g_p2eff[HID * 4];
__device__ float g_p2beff[4];
__device__ float g_pooled[Bn * C2];
__device__ float g_mod[Bn * Cc];

// ---- cp.async helpers ----
__device__ __forceinline__ uint32_t smem_u32(const void* p) {
    return (uint32_t)__cvta_generic_to_shared(p);
}
__device__ __forceinline__ void cpa4(uint32_t dst, const float* src, int sz) {
    asm volatile("cp.async.ca.shared.global [%0], [%1], 4, %2;" :: "r"(dst), "l"(src), "r"(sz));
}
__device__ __forceinline__ void cpa16(uint32_t dst, const float* src, int sz) {
    asm volatile("cp.async.ca.shared.global [%0], [%1], 16, %2;" :: "r"(dst), "l"(src), "r"(sz));
}
__device__ __forceinline__ void cpa_commit() { asm volatile("cp.async.commit_group;"); }
__device__ __forceinline__ void cpa_wait2() { asm volatile("cp.async.wait_group 2;"); }
__device__ __forceinline__ void cpa_wait1() { asm volatile("cp.async.wait_group 1;"); }
__device__ __forceinline__ void cpa_wait0() { asm volatile("cp.async.wait_group 0;"); }

// ---- tf32 mma ----
#define MMA_TF32(D, A, B0, B1) \
    asm volatile("mma.sync.aligned.m16n8k8.row.col.f32.tf32.tf32.f32 " \
        "{%0,%1,%2,%3}, {%4,%5,%6,%7}, {%8,%9}, {%0,%1,%2,%3};" \
        : "+f"((D)[0]), "+f"((D)[1]), "+f"((D)[2]), "+f"((D)[3]) \
        : "r"((A)[0]), "r"((A)[1]), "r"((A)[2]), "r"((A)[3]), "r"(B0), "r"(B1))

// ---------------- prep: pack p1 weights into mma B-fragment order, fold p2 ----------------
__global__ void prep_kernel(const float* __restrict__ p1w,
                            const float* __restrict__ p2w,
                            const float* __restrict__ p2b) {
    int idx = blockIdx.x * 256 + threadIdx.x;
    if (idx < 64 * 512) {
        int chunk = idx >> 9, rem = idx & 511;
        int q = rem >> 7, lrem = rem & 127;
        int ll = lrem >> 2, jj = lrem & 3;
        int j = q * 4 + jj, t = j >> 1, r = j & 1;
        int n = t * 8 + (ll >> 2);
        int k = chunk * 8 + (ll & 3) + r * 4;
        float v = p1w[n * 512 + k];
        uint32_t tf;
        asm("cvt.rna.tf32.f32 %0, %1;" : "=r"(tf) : "f"(v));
        g_wfrag[idx] = __uint_as_float(tf);
    }
    if (blockIdx.x == 0) {
        const float SC = 0.1f * 0.5f * 127.0f * 0.25f;
        if (threadIdx.x < HID) {
            int h = threadIdx.x;
            g_p2eff[h*4+0] = SC*(p2w[0*HID+h]+p2w[2*HID+h]+p2w[4*HID+h]+p2w[6*HID+h]);
            g_p2eff[h*4+1] = SC*(p2w[1*HID+h]+p2w[3*HID+h]+p2w[5*HID+h]+p2w[7*HID+h]);
            g_p2eff[h*4+2] = SC*(p2w[8*HID+h]+p2w[10*HID+h]+p2w[12*HID+h]+p2w[14*HID+h]);
            g_p2eff[h*4+3] = SC*(p2w[9*HID+h]+p2w[11*HID+h]+p2w[13*HID+h]+p2w[15*HID+h]);
        } else if (threadIdx.x < HID + 4) {
            int j = threadIdx.x - HID;
            int base = (j >> 1) * 8 + (j & 1);  // 0,1,8,9
            g_p2beff[j] = SC*(p2b[base]+p2b[base+2]+p2b[base+4]+p2b[base+6]);
        }
    }
}

// ---------------- GAP ----------------
__global__ void gap_kernel(const float* __restrict__ rgb, const float* __restrict__ tir) {
    int bc = blockIdx.x;               // 0..4095
    int b = bc >> 9, c2 = bc & 511;
    const float* src = (c2 < Cc) ? rgb + (size_t)(b * Cc + c2) * HW
                                 : tir + (size_t)(b * Cc + c2 - Cc) * HW;
    float s = 0.f;
    for (int i = threadIdx.x; i < HW; i += 256) s += src[i];
    __shared__ float sm[8];
    #pragma unroll
    for (int o = 16; o; o >>= 1) s += __shfl_xor_sync(0xffffffffu, s, o);
    if ((threadIdx.x & 31) == 0) sm[threadIdx.x >> 5] = s;
    __syncthreads();
    if (threadIdx.x < 8) {
        float v = sm[threadIdx.x];
        #pragma unroll
        for (int o = 4; o; o >>= 1) v += __shfl_xor_sync(0xffu, v, o);
        if (threadIdx.x == 0) g_pooled[bc] = v * (1.0f / (float)HW);
    }
}

// ---------------- modulation ----------------
__global__ void mod_kernel(const float* __restrict__ m1w, const float* __restrict__ m1b,
                           const float* __restrict__ m2w, const float* __restrict__ m2b) {
    int b = blockIdx.x;
    __shared__ float hid[HID];
    __shared__ float pl[C2];
    for (int i = threadIdx.x; i < C2; i += 256) pl[i] = g_pooled[b * C2 + i];
    __syncthreads();
    if (threadIdx.x < HID) {
        float s = m1b[threadIdx.x];
        const float* wr = m1w + threadIdx.x * C2;
        for (int c = 0; c < C2; c++) s = fmaf(wr[c], pl[c], s);
        hid[threadIdx.x] = fmaxf(s, 0.f);
    }
    __syncthreads();
    int o = threadIdx.x;
    float s = m2b[o];
    const float* wr = m2w + o * HID;
    #pragma unroll
    for (int h = 0; h < HID; h++) s = fmaf(wr[h], hid[h], s);
    g_mod[b * Cc + o] = 1.f / (1.f + expf(-s));
}

// ---------------- FUSED: depthwise 3x3 + tf32 tensor-core p1 GEMM + folded p2 ----------------
// Tile 32x8 = 256 px, 8 warps, 2 CTAs/SM (R11 base). Stage B = 8-px strip per thread
// (warp w handles channel w): 12 vector LDS instead of 72 scalar. ROWF=44 makes strip
// LDS.128s 4-phase optimal. XS relaid [ch][px] stride 264: STS.128 stores + conflict-free
// A-frag reads. Stage C = R11 tf32 mma (2 m-tiles x 8 n-tiles, d[64]).
#define TW 32
#define TH 8
#define ROWF 44            // floats per halo row (16B-aligned stride; banks (12py+8q) cover all groups)
#define CHT  440           // 10 * 44
#define TILEF (8 * CHT)    // 3520 floats per chunk buffer
#define CHK 8
#define NCHUNK (C2 / CHK)
#define NCP 800            // 16B granules per chunk (8ch * 10r * 10)
#define CHP 264            // XS channel stride (floats)

// dynamic smem layout (floats)
#define OFF_TILES 0                        // [4][3520]
#define OFF_XS    (OFF_TILES + 4*TILEF)    // [2][8*264]
#define OFF_WB    (OFF_XS + 2*(8*CHP))     // [4][512]
#define OFF_WDW   (OFF_WB + 4*512)         // [512*12]
#define SMEM_FLOATS (OFF_WDW + C2*12)
#define SMEM_BYTES  (SMEM_FLOATS * 4)

__global__ __launch_bounds__(256, 2)
void dwgemm_kernel(const float* __restrict__ rgb, const float* __restrict__ tir,
                   const float* __restrict__ dww, const float* __restrict__ dwb,
                   const float* __restrict__ p1b) {
    extern __shared__ __align__(16) float sm[];
    float* TILES = sm + OFF_TILES;
    float* XS    = sm + OFF_XS;
    float* WB    = sm + OFF_WB;
    float* WDW   = sm + OFF_WDW;

    const int tid = threadIdx.x;
    const int tx0 = blockIdx.x * TW;
    const int ty0 = blockIdx.y * TH;
    const int b   = blockIdx.z;
    const int w = tid >> 5;    // warp id
    const int l = tid & 31;    // lane

    // ---- chunk-invariant loader addressing (16B granules) ----
    int ofs[4], doff[4];
    unsigned vmask = 0;
    #pragma unroll
    for (int sl = 0; sl < 4; sl++) {
        int i = sl * 256 + tid;
        bool have = (i < NCP);
        int ii = have ? i : 0;
        int ch = ii / 100, rem = ii - ch * 100;
        int r = rem / 10, ci = rem - r * 10;
        int gy = ty0 + r - 1;
        int gx0 = tx0 - 4 + ci * 4;
        bool in = have && (gy >= 0) && (gy < Hh) && (gx0 >= 0) && (gx0 <= Ww - 4);
        ofs[sl]  = in ? (ch * HW + gy * Ww + gx0) : 0;
        doff[sl] = (ch * CHT + r * ROWF + ci * 4) * 4;
        if (in) vmask |= 1u << sl;
    }

    const float* rbase = rgb + (size_t)b * Cc * HW;
    const float* tbase = tir + (size_t)b * Cc * HW;
    const uint32_t tiles_a = smem_u32(TILES);
    const uint32_t wb_a    = smem_u32(WB);
    const uint32_t wdw_a   = smem_u32(WDW);

    auto load_chunk = [&](int chunk, int bt) {
        const float* base = (chunk < 32 ? rbase : tbase) + (size_t)((chunk & 31) * CHK) * HW;
        uint32_t dst0 = tiles_a + bt * (TILEF * 4);
        #pragma unroll
        for (int sl = 0; sl < 4; sl++) {
            if (sl < 3 || tid < (NCP - 768)) {
                int in = (vmask >> sl) & 1;
                cpa16(dst0 + doff[sl], base + ofs[sl], in ? 16 : 0);
            }
        }
        if (tid < 128)
            cpa16(wb_a + (bt * 512 + tid * 4) * 4, g_wfrag + chunk * 512 + tid * 4, 16);
    };

    // stage B: thread = 8-px strip x 1 channel (warp w -> channel w of the chunk)
    auto stageB = [&](int chunk, int bt, int xb) {
        const int py = l >> 2, pxx = (l & 3) * 8;
        const float* t0 = TILES + bt * TILEF + w * CHT + py * ROWF + pxx;
        const float* wd = WDW + chunk * (CHK * 12) + w * 12;
        float4 wa = *(const float4*)(wd);
        float4 wb = *(const float4*)(wd + 4);
        float2 wc = *(const float2*)(wd + 8);
        float o[8];
        #pragma unroll
        for (int j = 0; j < 8; j++) o[j] = wc.y;   // bias
        #pragma unroll
        for (int r = 0; r < 3; r++) {
            const float* tr = t0 + r * ROWF;
            float v[10];
            v[0] = tr[3];
            float4 q1 = *(const float4*)(tr + 4);
            float4 q2 = *(const float4*)(tr + 8);
            v[9] = tr[12];
            v[1]=q1.x; v[2]=q1.y; v[3]=q1.z; v[4]=q1.w;
            v[5]=q2.x; v[6]=q2.y; v[7]=q2.z; v[8]=q2.w;
            float w0 = (r==0)?wa.x:(r==1)?wa.w:wb.z;
            float w1 = (r==0)?wa.y:(r==1)?wb.x:wb.w;
            float w2 = (r==0)?wa.z:(r==1)?wb.y:wc.x;
            #pragma unroll
            for (int j = 0; j < 8; j++)
                o[j] = fmaf(w0, v[j], fmaf(w1, v[j+1], fmaf(w2, v[j+2], o[j])));
        }
        float* xp = XS + xb * (8 * CHP) + w * CHP + py * TW + pxx;
        *(float4*)xp       = make_float4(o[0], o[1], o[2], o[3]);
        *(float4*)(xp + 4) = make_float4(o[4], o[5], o[6], o[7]);
    };

    float d[64];
    #pragma unroll
    for (int i = 0; i < 64; i++) d[i] = 0.f;

    // prologue: dw taps (once) + chunks 0,1,2 in flight
    for (int i = tid; i < C2 * 12; i += 256) {
        int c2 = i / 12, k = i - c2 * 12;
        const float* src = (k < 9) ? dww + c2 * 9 + k : dwb + c2;
        cpa4(wdw_a + i * 4, src, (k <= 9) ? 4 : 0);
    }
    load_chunk(0, 0); cpa_commit();
    load_chunk(1, 1); cpa_commit();
    load_chunk(2, 2); cpa_commit();
    cpa_wait2();                 // taps + chunk 0 resident
    __syncthreads();
    stageB(0, 0, 0);

    for (int chunk = 0; chunk < NCHUNK; chunk++) {
        if (chunk + 2 < NCHUNK) cpa_wait1();
        else                    cpa_wait0();
        __syncthreads();

        if (chunk + 3 < NCHUNK) { load_chunk(chunk + 3, (chunk + 3) & 3); cpa_commit(); }
        if (chunk + 1 < NCHUNK) stageB(chunk + 1, (chunk + 1) & 3, (chunk + 1) & 1);

        // ---- stage C: tensor GEMM on XS[chunk&1] with WB[chunk&3] ----
        const float* xbp = XS + (chunk & 1) * (8 * CHP);
        const float4* B4 = (const float4*)(WB + (chunk & 3) * 512);
        uint32_t a[2][4];
        const int c = l & 3, row = l >> 2;
        #pragma unroll
        for (int m = 0; m < 2; m++) {
            int px = w * 32 + m * 16 + row;
            a[m][0] = __float_as_uint(xbp[c * CHP + px]);
            a[m][1] = __float_as_uint(xbp[c * CHP + px + 8]);
            a[m][2] = __float_as_uint(xbp[(c + 4) * CHP + px]);
            a[m][3] = __float_as_uint(xbp[(c + 4) * CHP + px + 8]);
        }
        #pragma unroll
        for (int q = 0; q < 4; q++) {
            float4 B = B4[q * 32 + l];
            uint32_t b0a = __float_as_uint(B.x), b1a = __float_as_uint(B.y);
            uint32_t b0b = __float_as_uint(B.z), b1b = __float_as_uint(B.w);
            #pragma unroll
            for (int m = 0; m < 2; m++) {
                MMA_TF32(d + (m * 8 + 2 * q) * 4,     a[m], b0a, b1a);
                MMA_TF32(d + (m * 8 + 2 * q + 1) * 4, a[m], b0b, b1b);
            }
        }
    }

    // ---- Epilogue: bias + ReLU + folded p2, quad-reduce over hid lanes ----
    float4 oA[2], oB[2];
    #pragma unroll
    for (int m = 0; m < 2; m++) {
        oA[m] = make_float4(0.f, 0.f, 0.f, 0.f);
        oB[m] = make_float4(0.f, 0.f, 0.f, 0.f);
    }
    const float4* P2 = (const float4*)g_p2eff;
    #pragma unroll
    for (int t = 0; t < 8; t++) {
        int h0 = t * 8 + (l & 3) * 2;
        float4 e0 = P2[h0], e1 = P2[h0 + 1];
        float bb0 = p1b[h0], bb1 = p1b[h0 + 1];
        #pragma unroll
        for (int m = 0; m < 2; m++) {
            const float* dd = d + (m * 8 + t) * 4;
            float r0 = fmaxf(dd[0] + bb0, 0.f), r1 = fmaxf(dd[1] + bb1, 0.f);
            float r2 = fmaxf(dd[2] + bb0, 0.f), r3 = fmaxf(dd[3] + bb1, 0.f);
            oA[m].x += e0.x * r0 + e1.x * r1;  oA[m].y += e0.y * r0 + e1.y * r1;
            oA[m].z += e0.z * r0 + e1.z * r1;  oA[m].w += e0.w * r0 + e1.w * r1;
            oB[m].x += e0.x * r2 + e1.x * r3;  oB[m].y += e0.y * r2 + e1.y * r3;
            oB[m].z += e0.z * r2 + e1.z * r3;  oB[m].w += e0.w * r2 + e1.w * r3;
        }
    }
    #pragma unroll
    for (int m = 0; m < 2; m++) {
        #pragma unroll
        for (int o = 1; o <= 2; o <<= 1) {
            oA[m].x += __shfl_xor_sync(0xffffffffu, oA[m].x, o);
            oA[m].y += __shfl_xor_sync(0xffffffffu, oA[m].y, o);
            oA[m].z += __shfl_xor_sync(0xffffffffu, oA[m].z, o);
            oA[m].w += __shfl_xor_sync(0xffffffffu, oA[m].w, o);
            oB[m].x += __shfl_xor_sync(0xffffffffu, oB[m].x, o);
            oB[m].y += __shfl_xor_sync(0xffffffffu, oB[m].y, o);
            oB[m].z += __shfl_xor_sync(0xffffffffu, oB[m].z, o);
            oB[m].w += __shfl_xor_sync(0xffffffffu, oB[m].w, o);
        }
    }
    if ((l & 3) == 0) {
        float4 bo = make_float4(g_p2beff[0], g_p2beff[1], g_p2beff[2], g_p2beff[3]);
        int py = ty0 + w;
        size_t base = (size_t)b * HW + py * Ww + tx0;
        #pragma unroll
        for (int m = 0; m < 2; m++) {
            int cA = m * 16 + (l >> 2);
            float4 sA = make_float4(oA[m].x + bo.x, oA[m].y + bo.y, oA[m].z + bo.z, oA[m].w + bo.w);
            float4 sB = make_float4(oB[m].x + bo.x, oB[m].y + bo.y, oB[m].z + bo.z, oB[m].w + bo.w);
            ((float4*)g_off)[base + cA]     = sA;
            ((float4*)g_off)[base + cA + 8] = sB;
        }
    }
}

// ---------------- bilinear sample + mod + quality ----------------
__global__ void sample_kernel(const float* __restrict__ rgb, const float* __restrict__ tir,
                              float* __restrict__ out) {
    int x = threadIdx.x;        // 128
    int y = blockIdx.x;         // 128
    int b = blockIdx.y;         // 8
    __shared__ float smod[Cc];
    for (int i = threadIdx.x; i < Cc; i += 128) smod[i] = g_mod[b * Cc + i];
    __syncthreads();
    int hw = y * Ww + x;
    int p = b * HW + hw;
    float4 off = ((const float4*)g_off)[p];

    float ixr = fminf(fmaxf((float)x + off.x, 0.f), 127.f);
    float iyr = fminf(fmaxf((float)y + off.y, 0.f), 127.f);
    float ixt = fminf(fmaxf((float)x + off.z, 0.f), 127.f);
    float iyt = fminf(fmaxf((float)y + off.w, 0.f), 127.f);

    float fx0r = floorf(ixr), fy0r = floorf(iyr);
    int x0r = (int)fx0r, y0r = (int)fy0r;
    int x1r = min(x0r + 1, 127), y1r = min(y0r + 1, 127);
    float wxr = ixr - fx0r, wyr = iyr - fy0r;
    int i00r = y0r*Ww + x0r, i01r = y0r*Ww + x1r, i10r = y1r*Ww + x0r, i11r = y1r*Ww + x1r;

    float fx0t = floorf(ixt), fy0t = floorf(iyt);
    int x0t = (int)fx0t, y0t = (int)fy0t;
    int x1t = min(x0t + 1, 127), y1t = min(y0t + 1, 127);
    float wxt = ixt - fx0t, wyt = iyt - fy0t;
    int i00t = y0t*Ww + x0t, i01t = y0t*Ww + x1t, i10t = y1t*Ww + x0t, i11t = y1t*Ww + x1t;

    const float* rb = rgb + (size_t)b * Cc * HW;
    const float* tb = tir + (size_t)b * Cc * HW;
    float* outR = out + (size_t)b * Cc * HW + hw;
    float* outT = out + (size_t)Bn * Cc * HW + (size_t)b * Cc * HW + hw;

    float qacc = 0.f;
    #pragma unroll 4
    for (int c = 0; c < Cc; c++) {
        size_t co = (size_t)c * HW;
        float v00 = rb[co + i00r], v01 = rb[co + i01r];
        float v10 = rb[co + i10r], v11 = rb[co + i11r];
        float topr = v00 * (1.f - wxr) + v01 * wxr;
        float botr = v10 * (1.f - wxr) + v11 * wxr;
        float rv = (topr * (1.f - wyr) + botr * wyr) * smod[c];

        float u00 = tb[co + i00t], u01 = tb[co + i01t];
        float u10 = tb[co + i10t], u11 = tb[co + i11t];
        float topt = u00 * (1.f - wxt) + u01 * wxt;
        float bott = u10 * (1.f - wxt) + u11 * wxt;
        float tv = (topt * (1.f - wyt) + bott * wyt) * smod[c];

        outR[co] = rv;
        outT[co] = tv;
        qacc += fabsf(rv - tv);
    }
    float q = 1.f - qacc * (1.f / (float)Cc);
    out[(size_t)2 * Bn * Cc * HW + p] = 1.f / (1.f + expf(-q));
}

extern "C" void kernel_launch(void* const* d_in, const int* in_sizes, int n_in,
                              void* d_out, int out_size) {
    const float* rgb  = (const float*)d_in[0];
    const float* tir  = (const float*)d_in[1];
    const float* dw_w = (const float*)d_in[2];
    const float* dw_b = (const float*)d_in[3];
    const float* p1_w = (const float*)d_in[4];
    const float* p1_b = (const float*)d_in[5];
    const float* p2_w = (const float*)d_in[6];
    const float* p2_b = (const float*)d_in[7];
    const float* m1_w = (const float*)d_in[8];
    const float* m1_b = (const float*)d_in[9];
    const float* m2_w = (const float*)d_in[10];
    const float* m2_b = (const float*)d_in[11];
    float* out = (float*)d_out;

    cudaFuncSetAttribute(dwgemm_kernel, cudaFuncAttributeMaxDynamicSharedMemorySize, SMEM_BYTES);

    prep_kernel<<<129, 256>>>(p1_w, p2_w, p2_b);
    gap_kernel<<<Bn * C2, 256>>>(rgb, tir);
    mod_kernel<<<Bn, 256>>>(m1_w, m1_b, m2_w, m2_b);
    dwgemm_kernel<<<dim3(Ww / TW, Hh / TH, Bn), 256, SMEM_BYTES>>>(rgb, tir, dw_w, dw_b, p1_b);
    sample_kernel<<<dim3(Hh, Bn), Ww>>>(rgb, tir, out);
}

// round 14
// speedup vs baseline: 1.3280x; 1.0766x over previous
#include <cuda_runtime.h>
#include <cuda_bf16.h>
#include <math.h>
#include <stdint.h>

#define Bn   8
#define Cc   256
#define C2   512
#define Hh   128
#define Ww   128
#define HW   16384
#define BHW  131072
#define HID  64

// Scratch (device globals: allocation-free rule)
__device__ float g_off[(size_t)BHW * 4];
__device__ float g_wfrag[C2 / 8 * 512];       // p1 weights in tf32 mma B-fragment order
__device__ float g_p2eff[HID * 4];
__device__ float g_p2beff[4];
__device__ float g_pooled[Bn * C2];
__device__ float g_mod[Bn * Cc];

// ---- cp.async helpers ----
__device__ __forceinline__ uint32_t smem_u32(const void* p) {
    return (uint32_t)__cvta_generic_to_shared(p);
}
__device__ __forceinline__ void cpa4(uint32_t dst, const float* src, int sz) {
    asm volatile("cp.async.ca.shared.global [%0], [%1], 4, %2;" :: "r"(dst), "l"(src), "r"(sz));
}
__device__ __forceinline__ void cpa16(uint32_t dst, const float* src, int sz) {
    asm volatile("cp.async.ca.shared.global [%0], [%1], 16, %2;" :: "r"(dst), "l"(src), "r"(sz));
}
__device__ __forceinline__ void cpa_commit() { asm volatile("cp.async.commit_group;"); }
__device__ __forceinline__ void cpa_wait2() { asm volatile("cp.async.wait_group 2;"); }
__device__ __forceinline__ void cpa_wait1() { asm volatile("cp.async.wait_group 1;"); }
__device__ __forceinline__ void cpa_wait0() { asm volatile("cp.async.wait_group 0;"); }

// ---- tf32 mma ----
#define MMA_TF32(D, A, B0, B1) \
    asm volatile("mma.sync.aligned.m16n8k8.row.col.f32.tf32.tf32.f32 " \
        "{%0,%1,%2,%3}, {%4,%5,%6,%7}, {%8,%9}, {%0,%1,%2,%3};" \
        : "+f"((D)[0]), "+f"((D)[1]), "+f"((D)[2]), "+f"((D)[3]) \
        : "r"((A)[0]), "r"((A)[1]), "r"((A)[2]), "r"((A)[3]), "r"(B0), "r"(B1))

// ---------------- prep: pack p1 weights into mma B-fragment order, fold p2, zero pooled ----------------
__global__ void prep_kernel(const float* __restrict__ p1w,
                            const float* __restrict__ p2w,
                            const float* __restrict__ p2b) {
    int idx = blockIdx.x * 256 + threadIdx.x;
    if (idx < 64 * 512) {
        int chunk = idx >> 9, rem = idx & 511;
        int q = rem >> 7, lrem = rem & 127;
        int ll = lrem >> 2, jj = lrem & 3;
        int j = q * 4 + jj, t = j >> 1, r = j & 1;
        int n = t * 8 + (ll >> 2);
        int k = chunk * 8 + (ll & 3) + r * 4;
        float v = p1w[n * 512 + k];
        uint32_t tf;
        asm("cvt.rna.tf32.f32 %0, %1;" : "=r"(tf) : "f"(v));
        g_wfrag[idx] = __uint_as_float(tf);
    }
    if (idx < Bn * C2) g_pooled[idx] = 0.f;
    if (blockIdx.x == 0) {
        const float SC = 0.1f * 0.5f * 127.0f * 0.25f;
        if (threadIdx.x < HID) {
            int h = threadIdx.x;
            g_p2eff[h*4+0] = SC*(p2w[0*HID+h]+p2w[2*HID+h]+p2w[4*HID+h]+p2w[6*HID+h]);
            g_p2eff[h*4+1] = SC*(p2w[1*HID+h]+p2w[3*HID+h]+p2w[5*HID+h]+p2w[7*HID+h]);
            g_p2eff[h*4+2] = SC*(p2w[8*HID+h]+p2w[10*HID+h]+p2w[12*HID+h]+p2w[14*HID+h]);
            g_p2eff[h*4+3] = SC*(p2w[9*HID+h]+p2w[11*HID+h]+p2w[13*HID+h]+p2w[15*HID+h]);
        } else if (threadIdx.x < HID + 4) {
            int j = threadIdx.x - HID;
            int base = (j >> 1) * 8 + (j & 1);  // 0,1,8,9
            g_p2beff[j] = SC*(p2b[base]+p2b[base+2]+p2b[base+4]+p2b[base+6]);
        }
    }
}

// ---------------- modulation (runs AFTER dwgemm; pooled holds raw sums) ----------------
__global__ void mod_kernel(const float* __restrict__ m1w, const float* __restrict__ m1b,
                           const float* __restrict__ m2w, const float* __restrict__ m2b) {
    int b = blockIdx.x;
    __shared__ float hid[HID];
    __shared__ float pl[C2];
    for (int i = threadIdx.x; i < C2; i += 256)
        pl[i] = g_pooled[b * C2 + i] * (1.0f / (float)HW);
    __syncthreads();
    if (threadIdx.x < HID) {
        float s = m1b[threadIdx.x];
        const float* wr = m1w + threadIdx.x * C2;
        for (int c = 0; c < C2; c++) s = fmaf(wr[c], pl[c], s);
        hid[threadIdx.x] = fmaxf(s, 0.f);
    }
    __syncthreads();
    int o = threadIdx.x;
    float s = m2b[o];
    const float* wr = m2w + o * HID;
    #pragma unroll
    for (int h = 0; h < HID; h++) s = fmaf(wr[h], hid[h], s);
    g_mod[b * Cc + o] = 1.f / (1.f + expf(-s));
}

// ---------------- FUSED: depthwise 3x3 + GAP + tf32 tensor-core p1 GEMM + folded p2 ----------------
// Tile 32x8 = 256 px, 8 warps, 2 CTAs/SM. Stage B = 8-px strip per thread (warp w =
// channel w); also accumulates the central-row sum -> warp shfl-reduce -> one
// atomicAdd per warp-chunk into g_pooled (replaces the 268MB gap kernel).
#define TW 32
#define TH 8
#define ROWF 44
#define CHT  440           // 10 * 44
#define TILEF (8 * CHT)    // 3520 floats per chunk buffer
#define CHK 8
#define NCHUNK (C2 / CHK)
#define NCP 800            // 16B granules per chunk (8ch * 10r * 10)
#define CHP 264            // XS channel stride (floats)

// dynamic smem layout (floats)
#define OFF_TILES 0                        // [4][3520]
#define OFF_XS    (OFF_TILES + 4*TILEF)    // [2][8*264]
#define OFF_WB    (OFF_XS + 2*(8*CHP))     // [4][512]
#define OFF_WDW   (OFF_WB + 4*512)         // [512*12]
#define SMEM_FLOATS (OFF_WDW + C2*12)
#define SMEM_BYTES  (SMEM_FLOATS * 4)

__global__ __launch_bounds__(256, 2)
void dwgemm_kernel(const float* __restrict__ rgb, const float* __restrict__ tir,
                   const float* __restrict__ dww, const float* __restrict__ dwb,
                   const float* __restrict__ p1b) {
    extern __shared__ __align__(16) float sm[];
    float* TILES = sm + OFF_TILES;
    float* XS    = sm + OFF_XS;
    float* WB    = sm + OFF_WB;
    float* WDW   = sm + OFF_WDW;

    const int tid = threadIdx.x;
    const int tx0 = blockIdx.x * TW;
    const int ty0 = blockIdx.y * TH;
    const int b   = blockIdx.z;
    const int w = tid >> 5;    // warp id
    const int l = tid & 31;    // lane

    // ---- chunk-invariant loader addressing (16B granules) ----
    int ofs[4], doff[4];
    unsigned vmask = 0;
    #pragma unroll
    for (int sl = 0; sl < 4; sl++) {
        int i = sl * 256 + tid;
        bool have = (i < NCP);
        int ii = have ? i : 0;
        int ch = ii / 100, rem = ii - ch * 100;
        int r = rem / 10, ci = rem - r * 10;
        int gy = ty0 + r - 1;
        int gx0 = tx0 - 4 + ci * 4;
        bool in = have && (gy >= 0) && (gy < Hh) && (gx0 >= 0) && (gx0 <= Ww - 4);
        ofs[sl]  = in ? (ch * HW + gy * Ww + gx0) : 0;
        doff[sl] = (ch * CHT + r * ROWF + ci * 4) * 4;
        if (in) vmask |= 1u << sl;
    }

    const float* rbase = rgb + (size_t)b * Cc * HW;
    const float* tbase = tir + (size_t)b * Cc * HW;
    const uint32_t tiles_a = smem_u32(TILES);
    const uint32_t wb_a    = smem_u32(WB);
    const uint32_t wdw_a   = smem_u32(WDW);

    auto load_chunk = [&](int chunk, int bt) {
        const float* base = (chunk < 32 ? rbase : tbase) + (size_t)((chunk & 31) * CHK) * HW;
        uint32_t dst0 = tiles_a + bt * (TILEF * 4);
        #pragma unroll
        for (int sl = 0; sl < 4; sl++) {
            if (sl < 3 || tid < (NCP - 768)) {
                int in = (vmask >> sl) & 1;
                cpa16(dst0 + doff[sl], base + ofs[sl], in ? 16 : 0);
            }
        }
        if (tid < 128)
            cpa16(wb_a + (bt * 512 + tid * 4) * 4, g_wfrag + chunk * 512 + tid * 4, 16);
    };

    // stage B: thread = 8-px strip x 1 channel (warp w -> channel w of the chunk)
    // Also accumulates the tile's central-row sum for GAP (g_pooled).
    auto stageB = [&](int chunk, int bt, int xb) {
        const int py = l >> 2, pxx = (l & 3) * 8;
        const float* t0 = TILES + bt * TILEF + w * CHT + py * ROWF + pxx;
        const float* wd = WDW + chunk * (CHK * 12) + w * 12;
        float4 wa = *(const float4*)(wd);
        float4 wb = *(const float4*)(wd + 4);
        float2 wc = *(const float2*)(wd + 8);
        float o[8];
        #pragma unroll
        for (int j = 0; j < 8; j++) o[j] = wc.y;   // bias
        float csum = 0.f;
        #pragma unroll
        for (int r = 0; r < 3; r++) {
            const float* tr = t0 + r * ROWF;
            float v[10];
            v[0] = tr[3];
            float4 q1 = *(const float4*)(tr + 4);
            float4 q2 = *(const float4*)(tr + 8);
            v[9] = tr[12];
            v[1]=q1.x; v[2]=q1.y; v[3]=q1.z; v[4]=q1.w;
            v[5]=q2.x; v[6]=q2.y; v[7]=q2.z; v[8]=q2.w;
            float w0 = (r==0)?wa.x:(r==1)?wa.w:wb.z;
            float w1 = (r==0)?wa.y:(r==1)?wb.x:wb.w;
            float w2 = (r==0)?wa.z:(r==1)?wb.y:wc.x;
            #pragma unroll
            for (int j = 0; j < 8; j++)
                o[j] = fmaf(w0, v[j], fmaf(w1, v[j+1], fmaf(w2, v[j+2], o[j])));
            if (r == 1)
                csum = ((v[1]+v[2])+(v[3]+v[4])) + ((v[5]+v[6])+(v[7]+v[8]));
        }
        float* xp = XS + xb * (8 * CHP) + w * CHP + py * TW + pxx;
        *(float4*)xp       = make_float4(o[0], o[1], o[2], o[3]);
        *(float4*)(xp + 4) = make_float4(o[4], o[5], o[6], o[7]);
        #pragma unroll
        for (int oo = 16; oo; oo >>= 1) csum += __shfl_xor_sync(0xffffffffu, csum, oo);
        if (l == 0) atomicAdd(&g_pooled[b * C2 + chunk * CHK + w], csum);
    };

    float d[64];
    #pragma unroll
    for (int i = 0; i < 64; i++) d[i] = 0.f;

    // prologue: dw taps (once) + chunks 0,1,2 in flight
    for (int i = tid; i < C2 * 12; i += 256) {
        int c2 = i / 12, k = i - c2 * 12;
        const float* src = (k < 9) ? dww + c2 * 9 + k : dwb + c2;
        cpa4(wdw_a + i * 4, src, (k <= 9) ? 4 : 0);
    }
    load_chunk(0, 0); cpa_commit();
    load_chunk(1, 1); cpa_commit();
    load_chunk(2, 2); cpa_commit();
    cpa_wait2();                 // taps + chunk 0 resident
    __syncthreads();
    stageB(0, 0, 0);

    for (int chunk = 0; chunk < NCHUNK; chunk++) {
        if (chunk + 2 < NCHUNK) cpa_wait1();
        else                    cpa_wait0();
        __syncthreads();

        if (chunk + 3 < NCHUNK) { load_chunk(chunk + 3, (chunk + 3) & 3); cpa_commit(); }
        if (chunk + 1 < NCHUNK) stageB(chunk + 1, (chunk + 1) & 3, (chunk + 1) & 1);

        // ---- stage C: tensor GEMM on XS[chunk&1] with WB[chunk&3] ----
        const float* xbp = XS + (chunk & 1) * (8 * CHP);
        const float4* B4 = (const float4*)(WB + (chunk & 3) * 512);
        uint32_t a[2][4];
        const int c = l & 3, row = l >> 2;
        #pragma unroll
        for (int m = 0; m < 2; m++) {
            int px = w * 32 + m * 16 + row;
            a[m][0] = __float_as_uint(xbp[c * CHP + px]);
            a[m][1] = __float_as_uint(xbp[c * CHP + px + 8]);
            a[m][2] = __float_as_uint(xbp[(c + 4) * CHP + px]);
            a[m][3] = __float_as_uint(xbp[(c + 4) * CHP + px + 8]);
        }
        #pragma unroll
        for (int q = 0; q < 4; q++) {
            float4 B = B4[q * 32 + l];
            uint32_t b0a = __float_as_uint(B.x), b1a = __float_as_uint(B.y);
            uint32_t b0b = __float_as_uint(B.z), b1b = __float_as_uint(B.w);
            #pragma unroll
            for (int m = 0; m < 2; m++) {
                MMA_TF32(d + (m * 8 + 2 * q) * 4,     a[m], b0a, b1a);
                MMA_TF32(d + (m * 8 + 2 * q + 1) * 4, a[m], b0b, b1b);
            }
        }
    }

    // ---- Epilogue: bias + ReLU + folded p2, quad-reduce over hid lanes ----
    float4 oA[2], oB[2];
    #pragma unroll
    for (int m = 0; m < 2; m++) {
        oA[m] = make_float4(0.f, 0.f, 0.f, 0.f);
        oB[m] = make_float4(0.f, 0.f, 0.f, 0.f);
    }
    const float4* P2 = (const float4*)g_p2eff;
    #pragma unroll
    for (int t = 0; t < 8; t++) {
        int h0 = t * 8 + (l & 3) * 2;
        float4 e0 = P2[h0], e1 = P2[h0 + 1];
        float bb0 = p1b[h0], bb1 = p1b[h0 + 1];
        #pragma unroll
        for (int m = 0; m < 2; m++) {
            const float* dd = d + (m * 8 + t) * 4;
            float r0 = fmaxf(dd[0] + bb0, 0.f), r1 = fmaxf(dd[1] + bb1, 0.f);
            float r2 = fmaxf(dd[2] + bb0, 0.f), r3 = fmaxf(dd[3] + bb1, 0.f);
            oA[m].x += e0.x * r0 + e1.x * r1;  oA[m].y += e0.y * r0 + e1.y * r1;
            oA[m].z += e0.z * r0 + e1.z * r1;  oA[m].w += e0.w * r0 + e1.w * r1;
            oB[m].x += e0.x * r2 + e1.x * r3;  oB[m].y += e0.y * r2 + e1.y * r3;
            oB[m].z += e0.z * r2 + e1.z * r3;  oB[m].w += e0.w * r2 + e1.w * r3;
        }
    }
    #pragma unroll
    for (int m = 0; m < 2; m++) {
        #pragma unroll
        for (int o = 1; o <= 2; o <<= 1) {
            oA[m].x += __shfl_xor_sync(0xffffffffu, oA[m].x, o);
            oA[m].y += __shfl_xor_sync(0xffffffffu, oA[m].y, o);
            oA[m].z += __shfl_xor_sync(0xffffffffu, oA[m].z, o);
            oA[m].w += __shfl_xor_sync(0xffffffffu, oA[m].w, o);
            oB[m].x += __shfl_xor_sync(0xffffffffu, oB[m].x, o);
            oB[m].y += __shfl_xor_sync(0xffffffffu, oB[m].y, o);
            oB[m].z += __shfl_xor_sync(0xffffffffu, oB[m].z, o);
            oB[m].w += __shfl_xor_sync(0xffffffffu, oB[m].w, o);
        }
    }
    if ((l & 3) == 0) {
        float4 bo = make_float4(g_p2beff[0], g_p2beff[1], g_p2beff[2], g_p2beff[3]);
        int py = ty0 + w;
        size_t base = (size_t)b * HW + py * Ww + tx0;
        #pragma unroll
        for (int m = 0; m < 2; m++) {
            int cA = m * 16 + (l >> 2);
            float4 sA = make_float4(oA[m].x + bo.x, oA[m].y + bo.y, oA[m].z + bo.z, oA[m].w + bo.w);
            float4 sB = make_float4(oB[m].x + bo.x, oB[m].y + bo.y, oB[m].z + bo.z, oB[m].w + bo.w);
            ((float4*)g_off)[base + cA]     = sA;
            ((float4*)g_off)[base + cA + 8] = sB;
        }
    }
}

// ---------------- bilinear sample + mod + quality ----------------
__global__ void sample_kernel(const float* __restrict__ rgb, const float* __restrict__ tir,
                              float* __restrict__ out) {
    int x = threadIdx.x;        // 128
    int y = blockIdx.x;         // 128
    int b = blockIdx.y;         // 8
    __shared__ float smod[Cc];
    for (int i = threadIdx.x; i < Cc; i += 128) smod[i] = g_mod[b * Cc + i];
    __syncthreads();
    int hw = y * Ww + x;
    int p = b * HW + hw;
    float4 off = ((const float4*)g_off)[p];

    float ixr = fminf(fmaxf((float)x + off.x, 0.f), 127.f);
    float iyr = fminf(fmaxf((float)y + off.y, 0.f), 127.f);
    float ixt = fminf(fmaxf((float)x + off.z, 0.f), 127.f);
    float iyt = fminf(fmaxf((float)y + off.w, 0.f), 127.f);

    float fx0r = floorf(ixr), fy0r = floorf(iyr);
    int x0r = (int)fx0r, y0r = (int)fy0r;
    int x1r = min(x0r + 1, 127), y1r = min(y0r + 1, 127);
    float wxr = ixr - fx0r, wyr = iyr - fy0r;
    int i00r = y0r*Ww + x0r, i01r = y0r*Ww + x1r, i10r = y1r*Ww + x0r, i11r = y1r*Ww + x1r;

    float fx0t = floorf(ixt), fy0t = floorf(iyt);
    int x0t = (int)fx0t, y0t = (int)fy0t;
    int x1t = min(x0t + 1, 127), y1t = min(y0t + 1, 127);
    float wxt = ixt - fx0t, wyt = iyt - fy0t;
    int i00t = y0t*Ww + x0t, i01t = y0t*Ww + x1t, i10t = y1t*Ww + x0t, i11t = y1t*Ww + x1t;

    const float* rb = rgb + (size_t)b * Cc * HW;
    const float* tb = tir + (size_t)b * Cc * HW;
    float* outR = out + (size_t)b * Cc * HW + hw;
    float* outT = out + (size_t)Bn * Cc * HW + (size_t)b * Cc * HW + hw;

    float qacc = 0.f;
    #pragma unroll 4
    for (int c = 0; c < Cc; c++) {
        size_t co = (size_t)c * HW;
        float v00 = rb[co + i00r], v01 = rb[co + i01r];
        float v10 = rb[co + i10r], v11 = rb[co + i11r];
        float topr = v00 * (1.f - wxr) + v01 * wxr;
        float botr = v10 * (1.f - wxr) + v11 * wxr;
        float rv = (topr * (1.f - wyr) + botr * wyr) * smod[c];

        float u00 = tb[co + i00t], u01 = tb[co + i01t];
        float u10 = tb[co + i10t], u11 = tb[co + i11t];
        float topt = u00 * (1.f - wxt) + u01 * wxt;
        float bott = u10 * (1.f - wxt) + u11 * wxt;
        float tv = (topt * (1.f - wyt) + bott * wyt) * smod[c];

        outR[co] = rv;
        outT[co] = tv;
        qacc += fabsf(rv - tv);
    }
    float q = 1.f - qacc * (1.f / (float)Cc);
    out[(size_t)2 * Bn * Cc * HW + p] = 1.f / (1.f + expf(-q));
}

extern "C" void kernel_launch(void* const* d_in, const int* in_sizes, int n_in,
                              void* d_out, int out_size) {
    const float* rgb  = (const float*)d_in[0];
    const float* tir  = (const float*)d_in[1];
    const float* dw_w = (const float*)d_in[2];
    const float* dw_b = (const float*)d_in[3];
    const float* p1_w = (const float*)d_in[4];
    const float* p1_b = (const float*)d_in[5];
    const float* p2_w = (const float*)d_in[6];
    const float* p2_b = (const float*)d_in[7];
    const float* m1_w = (const float*)d_in[8];
    const float* m1_b = (const float*)d_in[9];
    const float* m2_w = (const float*)d_in[10];
    const float* m2_b = (const float*)d_in[11];
    float* out = (float*)d_out;

    cudaFuncSetAttribute(dwgemm_kernel, cudaFuncAttributeMaxDynamicSharedMemorySize, SMEM_BYTES);

    prep_kernel<<<129, 256>>>(p1_w, p2_w, p2_b);
    dwgemm_kernel<<<dim3(Ww / TW, Hh / TH, Bn), 256, SMEM_BYTES>>>(rgb, tir, dw_w, dw_b, p1_b);
    mod_kernel<<<Bn, 256>>>(m1_w, m1_b, m2_w, m2_b);
    sample_kernel<<<dim3(Hh, Bn), Ww>>>(rgb, tir, out);
}

// round 15
// speedup vs baseline: 1.3461x; 1.0136x over previous
#include <cuda_runtime.h>
#include <cuda_bf16.h>
#include <math.h>
#include <stdint.h>

#define Bn   8
#define Cc   256
#define C2   512
#define Hh   128
#define Ww   128
#define HW   16384
#define BHW  131072
#define HID  64

// Scratch (device globals: allocation-free rule)
__device__ float g_off[(size_t)BHW * 4];
__device__ float g_wfrag[C2 / 8 * 512];       // p1 weights in tf32 mma B-fragment order
__device__ float g_p2eff[HID * 4];
__device__ float g_p2beff[4];
__device__ float g_pooled[Bn * C2];
__device__ float g_mod[Bn * Cc];
__device__ float g_qpart[2][(size_t)BHW];     // per-half quality partial sums

// ---- cp.async helpers ----
__device__ __forceinline__ uint32_t smem_u32(const void* p) {
    return (uint32_t)__cvta_generic_to_shared(p);
}
__device__ __forceinline__ void cpa4(uint32_t dst, const float* src, int sz) {
    asm volatile("cp.async.ca.shared.global [%0], [%1], 4, %2;" :: "r"(dst), "l"(src), "r"(sz));
}
__device__ __forceinline__ void cpa16(uint32_t dst, const float* src, int sz) {
    asm volatile("cp.async.ca.shared.global [%0], [%1], 16, %2;" :: "r"(dst), "l"(src), "r"(sz));
}
__device__ __forceinline__ void cpa_commit() { asm volatile("cp.async.commit_group;"); }
__device__ __forceinline__ void cpa_wait2() { asm volatile("cp.async.wait_group 2;"); }
__device__ __forceinline__ void cpa_wait1() { asm volatile("cp.async.wait_group 1;"); }
__device__ __forceinline__ void cpa_wait0() { asm volatile("cp.async.wait_group 0;"); }

// ---- tf32 mma ----
#define MMA_TF32(D, A, B0, B1) \
    asm volatile("mma.sync.aligned.m16n8k8.row.col.f32.tf32.tf32.f32 " \
        "{%0,%1,%2,%3}, {%4,%5,%6,%7}, {%8,%9}, {%0,%1,%2,%3};" \
        : "+f"((D)[0]), "+f"((D)[1]), "+f"((D)[2]), "+f"((D)[3]) \
        : "r"((A)[0]), "r"((A)[1]), "r"((A)[2]), "r"((A)[3]), "r"(B0), "r"(B1))

// ---------------- prep: pack p1 weights into mma B-fragment order, fold p2, zero pooled ----------------
__global__ void prep_kernel(const float* __restrict__ p1w,
                            const float* __restrict__ p2w,
                            const float* __restrict__ p2b) {
    int idx = blockIdx.x * 256 + threadIdx.x;
    if (idx < 64 * 512) {
        int chunk = idx >> 9, rem = idx & 511;
        int q = rem >> 7, lrem = rem & 127;
        int ll = lrem >> 2, jj = lrem & 3;
        int j = q * 4 + jj, t = j >> 1, r = j & 1;
        int n = t * 8 + (ll >> 2);
        int k = chunk * 8 + (ll & 3) + r * 4;
        float v = p1w[n * 512 + k];
        uint32_t tf;
        asm("cvt.rna.tf32.f32 %0, %1;" : "=r"(tf) : "f"(v));
        g_wfrag[idx] = __uint_as_float(tf);
    }
    if (idx < Bn * C2) g_pooled[idx] = 0.f;
    if (blockIdx.x == 0) {
        const float SC = 0.1f * 0.5f * 127.0f * 0.25f;
        if (threadIdx.x < HID) {
            int h = threadIdx.x;
            g_p2eff[h*4+0] = SC*(p2w[0*HID+h]+p2w[2*HID+h]+p2w[4*HID+h]+p2w[6*HID+h]);
            g_p2eff[h*4+1] = SC*(p2w[1*HID+h]+p2w[3*HID+h]+p2w[5*HID+h]+p2w[7*HID+h]);
            g_p2eff[h*4+2] = SC*(p2w[8*HID+h]+p2w[10*HID+h]+p2w[12*HID+h]+p2w[14*HID+h]);
            g_p2eff[h*4+3] = SC*(p2w[9*HID+h]+p2w[11*HID+h]+p2w[13*HID+h]+p2w[15*HID+h]);
        } else if (threadIdx.x < HID + 4) {
            int j = threadIdx.x - HID;
            int base = (j >> 1) * 8 + (j & 1);  // 0,1,8,9
            g_p2beff[j] = SC*(p2b[base]+p2b[base+2]+p2b[base+4]+p2b[base+6]);
        }
    }
}

// ---------------- modulation (runs AFTER dwgemm; pooled holds raw sums) ----------------
__global__ void mod_kernel(const float* __restrict__ m1w, const float* __restrict__ m1b,
                           const float* __restrict__ m2w, const float* __restrict__ m2b) {
    int b = blockIdx.x;
    __shared__ float hid[HID];
    __shared__ float pl[C2];
    for (int i = threadIdx.x; i < C2; i += 256)
        pl[i] = g_pooled[b * C2 + i] * (1.0f / (float)HW);
    __syncthreads();
    if (threadIdx.x < HID) {
        float s = m1b[threadIdx.x];
        const float* wr = m1w + threadIdx.x * C2;
        for (int c = 0; c < C2; c++) s = fmaf(wr[c], pl[c], s);
        hid[threadIdx.x] = fmaxf(s, 0.f);
    }
    __syncthreads();
    int o = threadIdx.x;
    float s = m2b[o];
    const float* wr = m2w + o * HID;
    #pragma unroll
    for (int h = 0; h < HID; h++) s = fmaf(wr[h], hid[h], s);
    g_mod[b * Cc + o] = 1.f / (1.f + expf(-s));
}

// ---------------- FUSED: depthwise 3x3 + GAP + tf32 tensor-core p1 GEMM + folded p2 ----------------
#define TW 32
#define TH 8
#define ROWF 44
#define CHT  440           // 10 * 44
#define TILEF (8 * CHT)    // 3520 floats per chunk buffer
#define CHK 8
#define NCHUNK (C2 / CHK)
#define NCP 800            // 16B granules per chunk (8ch * 10r * 10)
#define CHP 264            // XS channel stride (floats)

// dynamic smem layout (floats)
#define OFF_TILES 0                        // [4][3520]
#define OFF_XS    (OFF_TILES + 4*TILEF)    // [2][8*264]
#define OFF_WB    (OFF_XS + 2*(8*CHP))     // [4][512]
#define OFF_WDW   (OFF_WB + 4*512)         // [512*12]
#define SMEM_FLOATS (OFF_WDW + C2*12)
#define SMEM_BYTES  (SMEM_FLOATS * 4)

__global__ __launch_bounds__(256, 2)
void dwgemm_kernel(const float* __restrict__ rgb, const float* __restrict__ tir,
                   const float* __restrict__ dww, const float* __restrict__ dwb,
                   const float* __restrict__ p1b) {
    extern __shared__ __align__(16) float sm[];
    float* TILES = sm + OFF_TILES;
    float* XS    = sm + OFF_XS;
    float* WB    = sm + OFF_WB;
    float* WDW   = sm + OFF_WDW;

    const int tid = threadIdx.x;
    const int tx0 = blockIdx.x * TW;
    const int ty0 = blockIdx.y * TH;
    const int b   = blockIdx.z;
    const int w = tid >> 5;    // warp id
    const int l = tid & 31;    // lane

    // ---- chunk-invariant loader addressing (16B granules) ----
    int ofs[4], doff[4];
    unsigned vmask = 0;
    #pragma unroll
    for (int sl = 0; sl < 4; sl++) {
        int i = sl * 256 + tid;
        bool have = (i < NCP);
        int ii = have ? i : 0;
        int ch = ii / 100, rem = ii - ch * 100;
        int r = rem / 10, ci = rem - r * 10;
        int gy = ty0 + r - 1;
        int gx0 = tx0 - 4 + ci * 4;
        bool in = have && (gy >= 0) && (gy < Hh) && (gx0 >= 0) && (gx0 <= Ww - 4);
        ofs[sl]  = in ? (ch * HW + gy * Ww + gx0) : 0;
        doff[sl] = (ch * CHT + r * ROWF + ci * 4) * 4;
        if (in) vmask |= 1u << sl;
    }

    const float* rbase = rgb + (size_t)b * Cc * HW;
    const float* tbase = tir + (size_t)b * Cc * HW;
    const uint32_t tiles_a = smem_u32(TILES);
    const uint32_t wb_a    = smem_u32(WB);
    const uint32_t wdw_a   = smem_u32(WDW);

    auto load_chunk = [&](int chunk, int bt) {
        const float* base = (chunk < 32 ? rbase : tbase) + (size_t)((chunk & 31) * CHK) * HW;
        uint32_t dst0 = tiles_a + bt * (TILEF * 4);
        #pragma unroll
        for (int sl = 0; sl < 4; sl++) {
            if (sl < 3 || tid < (NCP - 768)) {
                int in = (vmask >> sl) & 1;
                cpa16(dst0 + doff[sl], base + ofs[sl], in ? 16 : 0);
            }
        }
        if (tid < 128)
            cpa16(wb_a + (bt * 512 + tid * 4) * 4, g_wfrag + chunk * 512 + tid * 4, 16);
    };

    // stage B: thread = 8-px strip x 1 channel (warp w -> channel w of the chunk)
    // Also accumulates the tile's central-row sum for GAP (g_pooled).
    auto stageB = [&](int chunk, int bt, int xb) {
        const int py = l >> 2, pxx = (l & 3) * 8;
        const float* t0 = TILES + bt * TILEF + w * CHT + py * ROWF + pxx;
        const float* wd = WDW + chunk * (CHK * 12) + w * 12;
        float4 wa = *(const float4*)(wd);
        float4 wb = *(const float4*)(wd + 4);
        float2 wc = *(const float2*)(wd + 8);
        float o[8];
        #pragma unroll
        for (int j = 0; j < 8; j++) o[j] = wc.y;   // bias
        float csum = 0.f;
        #pragma unroll
        for (int r = 0; r < 3; r++) {
            const float* tr = t0 + r * ROWF;
            float v[10];
            v[0] = tr[3];
            float4 q1 = *(const float4*)(tr + 4);
            float4 q2 = *(const float4*)(tr + 8);
            v[9] = tr[12];
            v[1]=q1.x; v[2]=q1.y; v[3]=q1.z; v[4]=q1.w;
            v[5]=q2.x; v[6]=q2.y; v[7]=q2.z; v[8]=q2.w;
            float w0 = (r==0)?wa.x:(r==1)?wa.w:wb.z;
            float w1 = (r==0)?wa.y:(r==1)?wb.x:wb.w;
            float w2 = (r==0)?wa.z:(r==1)?wb.y:wc.x;
            #pragma unroll
            for (int j = 0; j < 8; j++)
                o[j] = fmaf(w0, v[j], fmaf(w1, v[j+1], fmaf(w2, v[j+2], o[j])));
            if (r == 1)
                csum = ((v[1]+v[2])+(v[3]+v[4])) + ((v[5]+v[6])+(v[7]+v[8]));
        }
        float* xp = XS + xb * (8 * CHP) + w * CHP + py * TW + pxx;
        *(float4*)xp       = make_float4(o[0], o[1], o[2], o[3]);
        *(float4*)(xp + 4) = make_float4(o[4], o[5], o[6], o[7]);
        #pragma unroll
        for (int oo = 16; oo; oo >>= 1) csum += __shfl_xor_sync(0xffffffffu, csum, oo);
        if (l == 0) atomicAdd(&g_pooled[b * C2 + chunk * CHK + w], csum);
    };

    float d[64];
    #pragma unroll
    for (int i = 0; i < 64; i++) d[i] = 0.f;

    // prologue: dw taps (once) + chunks 0,1,2 in flight
    for (int i = tid; i < C2 * 12; i += 256) {
        int c2 = i / 12, k = i - c2 * 12;
        const float* src = (k < 9) ? dww + c2 * 9 + k : dwb + c2;
        cpa4(wdw_a + i * 4, src, (k <= 9) ? 4 : 0);
    }
    load_chunk(0, 0); cpa_commit();
    load_chunk(1, 1); cpa_commit();
    load_chunk(2, 2); cpa_commit();
    cpa_wait2();                 // taps + chunk 0 resident
    __syncthreads();
    stageB(0, 0, 0);

    for (int chunk = 0; chunk < NCHUNK; chunk++) {
        if (chunk + 2 < NCHUNK) cpa_wait1();
        else                    cpa_wait0();
        __syncthreads();

        if (chunk + 3 < NCHUNK) { load_chunk(chunk + 3, (chunk + 3) & 3); cpa_commit(); }
        if (chunk + 1 < NCHUNK) stageB(chunk + 1, (chunk + 1) & 3, (chunk + 1) & 1);

        // ---- stage C: tensor GEMM on XS[chunk&1] with WB[chunk&3] ----
        const float* xbp = XS + (chunk & 1) * (8 * CHP);
        const float4* B4 = (const float4*)(WB + (chunk & 3) * 512);
        uint32_t a[2][4];
        const int c = l & 3, row = l >> 2;
        #pragma unroll
        for (int m = 0; m < 2; m++) {
            int px = w * 32 + m * 16 + row;
            a[m][0] = __float_as_uint(xbp[c * CHP + px]);
            a[m][1] = __float_as_uint(xbp[c * CHP + px + 8]);
            a[m][2] = __float_as_uint(xbp[(c + 4) * CHP + px]);
            a[m][3] = __float_as_uint(xbp[(c + 4) * CHP + px + 8]);
        }
        #pragma unroll
        for (int q = 0; q < 4; q++) {
            float4 B = B4[q * 32 + l];
            uint32_t b0a = __float_as_uint(B.x), b1a = __float_as_uint(B.y);
            uint32_t b0b = __float_as_uint(B.z), b1b = __float_as_uint(B.w);
            #pragma unroll
            for (int m = 0; m < 2; m++) {
                MMA_TF32(d + (m * 8 + 2 * q) * 4,     a[m], b0a, b1a);
                MMA_TF32(d + (m * 8 + 2 * q + 1) * 4, a[m], b0b, b1b);
            }
        }
    }

    // ---- Epilogue: bias + ReLU + folded p2, quad-reduce over hid lanes ----
    float4 oA[2], oB[2];
    #pragma unroll
    for (int m = 0; m < 2; m++) {
        oA[m] = make_float4(0.f, 0.f, 0.f, 0.f);
        oB[m] = make_float4(0.f, 0.f, 0.f, 0.f);
    }
    const float4* P2 = (const float4*)g_p2eff;
    #pragma unroll
    for (int t = 0; t < 8; t++) {
        int h0 = t * 8 + (l & 3) * 2;
        float4 e0 = P2[h0], e1 = P2[h0 + 1];
        float bb0 = p1b[h0], bb1 = p1b[h0 + 1];
        #pragma unroll
        for (int m = 0; m < 2; m++) {
            const float* dd = d + (m * 8 + t) * 4;
            float r0 = fmaxf(dd[0] + bb0, 0.f), r1 = fmaxf(dd[1] + bb1, 0.f);
            float r2 = fmaxf(dd[2] + bb0, 0.f), r3 = fmaxf(dd[3] + bb1, 0.f);
            oA[m].x += e0.x * r0 + e1.x * r1;  oA[m].y += e0.y * r0 + e1.y * r1;
            oA[m].z += e0.z * r0 + e1.z * r1;  oA[m].w += e0.w * r0 + e1.w * r1;
            oB[m].x += e0.x * r2 + e1.x * r3;  oB[m].y += e0.y * r2 + e1.y * r3;
            oB[m].z += e0.z * r2 + e1.z * r3;  oB[m].w += e0.w * r2 + e1.w * r3;
        }
    }
    #pragma unroll
    for (int m = 0; m < 2; m++) {
        #pragma unroll
        for (int o = 1; o <= 2; o <<= 1) {
            oA[m].x += __shfl_xor_sync(0xffffffffu, oA[m].x, o);
            oA[m].y += __shfl_xor_sync(0xffffffffu, oA[m].y, o);
            oA[m].z += __shfl_xor_sync(0xffffffffu, oA[m].z, o);
            oA[m].w += __shfl_xor_sync(0xffffffffu, oA[m].w, o);
            oB[m].x += __shfl_xor_sync(0xffffffffu, oB[m].x, o);
            oB[m].y += __shfl_xor_sync(0xffffffffu, oB[m].y, o);
            oB[m].z += __shfl_xor_sync(0xffffffffu, oB[m].z, o);
            oB[m].w += __shfl_xor_sync(0xffffffffu, oB[m].w, o);
        }
    }
    if ((l & 3) == 0) {
        float4 bo = make_float4(g_p2beff[0], g_p2beff[1], g_p2beff[2], g_p2beff[3]);
        int py = ty0 + w;
        size_t base = (size_t)b * HW + py * Ww + tx0;
        #pragma unroll
        for (int m = 0; m < 2; m++) {
            int cA = m * 16 + (l >> 2);
            float4 sA = make_float4(oA[m].x + bo.x, oA[m].y + bo.y, oA[m].z + bo.z, oA[m].w + bo.w);
            float4 sB = make_float4(oB[m].x + bo.x, oB[m].y + bo.y, oB[m].z + bo.z, oB[m].w + bo.w);
            ((float4*)g_off)[base + cA]     = sA;
            ((float4*)g_off)[base + cA + 8] = sB;
        }
    }
}

// ---------------- bilinear sample + mod (channel-split halves) ----------------
__global__ void sample_kernel(const float* __restrict__ rgb, const float* __restrict__ tir,
                              float* __restrict__ out) {
    int x = threadIdx.x;        // 128
    int y = blockIdx.x;         // 128
    int b = blockIdx.y;         // 8
    int half = blockIdx.z;      // 0/1 -> channels [half*128, half*128+128)
    int c0 = half * 128;
    __shared__ float smod[128];
    smod[threadIdx.x] = g_mod[b * Cc + c0 + threadIdx.x];
    __syncthreads();
    int hw = y * Ww + x;
    int p = b * HW + hw;
    float4 off = ((const float4*)g_off)[p];

    float ixr = fminf(fmaxf((float)x + off.x, 0.f), 127.f);
    float iyr = fminf(fmaxf((float)y + off.y, 0.f), 127.f);
    float ixt = fminf(fmaxf((float)x + off.z, 0.f), 127.f);
    float iyt = fminf(fmaxf((float)y + off.w, 0.f), 127.f);

    float fx0r = floorf(ixr), fy0r = floorf(iyr);
    int x0r = (int)fx0r, y0r = (int)fy0r;
    int x1r = min(x0r + 1, 127), y1r = min(y0r + 1, 127);
    float wxr = ixr - fx0r, wyr = iyr - fy0r;
    int i00r = y0r*Ww + x0r, i01r = y0r*Ww + x1r, i10r = y1r*Ww + x0r, i11r = y1r*Ww + x1r;

    float fx0t = floorf(ixt), fy0t = floorf(iyt);
    int x0t = (int)fx0t, y0t = (int)fy0t;
    int x1t = min(x0t + 1, 127), y1t = min(y0t + 1, 127);
    float wxt = ixt - fx0t, wyt = iyt - fy0t;
    int i00t = y0t*Ww + x0t, i01t = y0t*Ww + x1t, i10t = y1t*Ww + x0t, i11t = y1t*Ww + x1t;

    const float* rb = rgb + ((size_t)b * Cc + c0) * HW;
    const float* tb = tir + ((size_t)b * Cc + c0) * HW;
    float* outR = out + ((size_t)b * Cc + c0) * HW + hw;
    float* outT = out + (size_t)Bn * Cc * HW + ((size_t)b * Cc + c0) * HW + hw;

    float qacc = 0.f;
    #pragma unroll 4
    for (int c = 0; c < 128; c++) {
        size_t co = (size_t)c * HW;
        float v00 = rb[co + i00r], v01 = rb[co + i01r];
        float v10 = rb[co + i10r], v11 = rb[co + i11r];
        float topr = v00 * (1.f - wxr) + v01 * wxr;
        float botr = v10 * (1.f - wxr) + v11 * wxr;
        float rv = (topr * (1.f - wyr) + botr * wyr) * smod[c];

        float u00 = tb[co + i00t], u01 = tb[co + i01t];
        float u10 = tb[co + i10t], u11 = tb[co + i11t];
        float topt = u00 * (1.f - wxt) + u01 * wxt;
        float bott = u10 * (1.f - wxt) + u11 * wxt;
        float tv = (topt * (1.f - wyt) + bott * wyt) * smod[c];

        outR[co] = rv;
        outT[co] = tv;
        qacc += fabsf(rv - tv);
    }
    g_qpart[half][p] = qacc;
}

// ---------------- quality epilogue ----------------
__global__ void qual_kernel(float* __restrict__ out) {
    int p = blockIdx.x * 256 + threadIdx.x;
    float q = 1.f - (g_qpart[0][p] + g_qpart[1][p]) * (1.f / (float)Cc);
    out[(size_t)2 * Bn * Cc * HW + p] = 1.f / (1.f + expf(-q));
}

extern "C" void kernel_launch(void* const* d_in, const int* in_sizes, int n_in,
                              void* d_out, int out_size) {
    const float* rgb  = (const float*)d_in[0];
    const float* tir  = (const float*)d_in[1];
    const float* dw_w = (const float*)d_in[2];
    const float* dw_b = (const float*)d_in[3];
    const float* p1_w = (const float*)d_in[4];
    const float* p1_b = (const float*)d_in[5];
    const float* p2_w = (const float*)d_in[6];
    const float* p2_b = (const float*)d_in[7];
    const float* m1_w = (const float*)d_in[8];
    const float* m1_b = (const float*)d_in[9];
    const float* m2_w = (const float*)d_in[10];
    const float* m2_b = (const float*)d_in[11];
    float* out = (float*)d_out;

    cudaFuncSetAttribute(dwgemm_kernel, cudaFuncAttributeMaxDynamicSharedMemorySize, SMEM_BYTES);

    prep_kernel<<<129, 256>>>(p1_w, p2_w, p2_b);
    dwgemm_kernel<<<dim3(Ww / TW, Hh / TH, Bn), 256, SMEM_BYTES>>>(rgb, tir, dw_w, dw_b, p1_b);
    mod_kernel<<<Bn, 256>>>(m1_w, m1_b, m2_w, m2_b);
    sample_kernel<<<dim3(Hh, Bn, 2), Ww>>>(rgb, tir, out);
    qual_kernel<<<BHW / 256, 256>>>(out);
}

// round 16
// speedup vs baseline: 1.3497x; 1.0027x over previous
#include <cuda_runtime.h>
#include <cuda_bf16.h>
#include <math.h>
#include <stdint.h>

#define Bn   8
#define Cc   256
#define C2   512
#define Hh   128
#define Ww   128
#define HW   16384
#define BHW  131072
#define HID  64

// Scratch (device globals: allocation-free rule)
__device__ float g_off[(size_t)BHW * 4];
__device__ float g_wfrag[C2 / 8 * 512];       // p1 weights in tf32 mma B-fragment order
__device__ float g_p2eff[HID * 4];
__device__ float g_p2beff[4];
__device__ float g_pooled[Bn * C2];
__device__ float g_mod[Bn * Cc];
__device__ float g_qpart[4][(size_t)BHW];     // per-quarter quality partial sums

// ---- cp.async helpers ----
__device__ __forceinline__ uint32_t smem_u32(const void* p) {
    return (uint32_t)__cvta_generic_to_shared(p);
}
__device__ __forceinline__ void cpa4(uint32_t dst, const float* src, int sz) {
    asm volatile("cp.async.ca.shared.global [%0], [%1], 4, %2;" :: "r"(dst), "l"(src), "r"(sz));
}
__device__ __forceinline__ void cpa16(uint32_t dst, const float* src, int sz) {
    asm volatile("cp.async.ca.shared.global [%0], [%1], 16, %2;" :: "r"(dst), "l"(src), "r"(sz));
}
__device__ __forceinline__ void cpa_commit() { asm volatile("cp.async.commit_group;"); }
__device__ __forceinline__ void cpa_wait2() { asm volatile("cp.async.wait_group 2;"); }
__device__ __forceinline__ void cpa_wait1() { asm volatile("cp.async.wait_group 1;"); }
__device__ __forceinline__ void cpa_wait0() { asm volatile("cp.async.wait_group 0;"); }

// ---- tf32 mma ----
#define MMA_TF32(D, A, B0, B1) \
    asm volatile("mma.sync.aligned.m16n8k8.row.col.f32.tf32.tf32.f32 " \
        "{%0,%1,%2,%3}, {%4,%5,%6,%7}, {%8,%9}, {%0,%1,%2,%3};" \
        : "+f"((D)[0]), "+f"((D)[1]), "+f"((D)[2]), "+f"((D)[3]) \
        : "r"((A)[0]), "r"((A)[1]), "r"((A)[2]), "r"((A)[3]), "r"(B0), "r"(B1))

// ---------------- prep: pack p1 weights into mma B-fragment order, fold p2, zero pooled ----------------
__global__ void prep_kernel(const float* __restrict__ p1w,
                            const float* __restrict__ p2w,
                            const float* __restrict__ p2b) {
    int idx = blockIdx.x * 256 + threadIdx.x;
    if (idx < 64 * 512) {
        int chunk = idx >> 9, rem = idx & 511;
        int q = rem >> 7, lrem = rem & 127;
        int ll = lrem >> 2, jj = lrem & 3;
        int j = q * 4 + jj, t = j >> 1, r = j & 1;
        int n = t * 8 + (ll >> 2);
        int k = chunk * 8 + (ll & 3) + r * 4;
        float v = p1w[n * 512 + k];
        uint32_t tf;
        asm("cvt.rna.tf32.f32 %0, %1;" : "=r"(tf) : "f"(v));
        g_wfrag[idx] = __uint_as_float(tf);
    }
    if (idx < Bn * C2) g_pooled[idx] = 0.f;
    if (blockIdx.x == 0) {
        const float SC = 0.1f * 0.5f * 127.0f * 0.25f;
        if (threadIdx.x < HID) {
            int h = threadIdx.x;
            g_p2eff[h*4+0] = SC*(p2w[0*HID+h]+p2w[2*HID+h]+p2w[4*HID+h]+p2w[6*HID+h]);
            g_p2eff[h*4+1] = SC*(p2w[1*HID+h]+p2w[3*HID+h]+p2w[5*HID+h]+p2w[7*HID+h]);
            g_p2eff[h*4+2] = SC*(p2w[8*HID+h]+p2w[10*HID+h]+p2w[12*HID+h]+p2w[14*HID+h]);
            g_p2eff[h*4+3] = SC*(p2w[9*HID+h]+p2w[11*HID+h]+p2w[13*HID+h]+p2w[15*HID+h]);
        } else if (threadIdx.x < HID + 4) {
            int j = threadIdx.x - HID;
            int base = (j >> 1) * 8 + (j & 1);  // 0,1,8,9
            g_p2beff[j] = SC*(p2b[base]+p2b[base+2]+p2b[base+4]+p2b[base+6]);
        }
    }
}

// ---------------- modulation (runs AFTER dwgemm; pooled holds raw sums) ----------------
__global__ void mod_kernel(const float* __restrict__ m1w, const float* __restrict__ m1b,
                           const float* __restrict__ m2w, const float* __restrict__ m2b) {
    int b = blockIdx.x;
    __shared__ float hid[HID];
    __shared__ float pl[C2];
    for (int i = threadIdx.x; i < C2; i += 256)
        pl[i] = g_pooled[b * C2 + i] * (1.0f / (float)HW);
    __syncthreads();
    if (threadIdx.x < HID) {
        float s = m1b[threadIdx.x];
        const float* wr = m1w + threadIdx.x * C2;
        for (int c = 0; c < C2; c++) s = fmaf(wr[c], pl[c], s);
        hid[threadIdx.x] = fmaxf(s, 0.f);
    }
    __syncthreads();
    int o = threadIdx.x;
    float s = m2b[o];
    const float* wr = m2w + o * HID;
    #pragma unroll
    for (int h = 0; h < HID; h++) s = fmaf(wr[h], hid[h], s);
    g_mod[b * Cc + o] = 1.f / (1.f + expf(-s));
}

// ---------------- FUSED: depthwise 3x3 + GAP + tf32 tensor-core p1 GEMM + folded p2 ----------------
#define TW 32
#define TH 8
#define ROWF 44
#define CHT  440           // 10 * 44
#define TILEF (8 * CHT)    // 3520 floats per chunk buffer
#define CHK 8
#define NCHUNK (C2 / CHK)
#define NCP 800            // 16B granules per chunk (8ch * 10r * 10)
#define CHP 264            // XS channel stride (floats)

// dynamic smem layout (floats)
#define OFF_TILES 0                        // [4][3520]
#define OFF_XS    (OFF_TILES + 4*TILEF)    // [2][8*264]
#define OFF_WB    (OFF_XS + 2*(8*CHP))     // [4][512]
#define OFF_WDW   (OFF_WB + 4*512)         // [512*12]
#define SMEM_FLOATS (OFF_WDW + C2*12)
#define SMEM_BYTES  (SMEM_FLOATS * 4)

__global__ __launch_bounds__(256, 2)
void dwgemm_kernel(const float* __restrict__ rgb, const float* __restrict__ tir,
                   const float* __restrict__ dww, const float* __restrict__ dwb,
                   const float* __restrict__ p1b) {
    extern __shared__ __align__(16) float sm[];
    float* TILES = sm + OFF_TILES;
    float* XS    = sm + OFF_XS;
    float* WB    = sm + OFF_WB;
    float* WDW   = sm + OFF_WDW;

    const int tid = threadIdx.x;
    const int tx0 = blockIdx.x * TW;
    const int ty0 = blockIdx.y * TH;
    const int b   = blockIdx.z;
    const int w = tid >> 5;    // warp id
    const int l = tid & 31;    // lane

    // ---- chunk-invariant loader addressing (16B granules) ----
    int ofs[4], doff[4];
    unsigned vmask = 0;
    #pragma unroll
    for (int sl = 0; sl < 4; sl++) {
        int i = sl * 256 + tid;
        bool have = (i < NCP);
        int ii = have ? i : 0;
        int ch = ii / 100, rem = ii - ch * 100;
        int r = rem / 10, ci = rem - r * 10;
        int gy = ty0 + r - 1;
        int gx0 = tx0 - 4 + ci * 4;
        bool in = have && (gy >= 0) && (gy < Hh) && (gx0 >= 0) && (gx0 <= Ww - 4);
        ofs[sl]  = in ? (ch * HW + gy * Ww + gx0) : 0;
        doff[sl] = (ch * CHT + r * ROWF + ci * 4) * 4;
        if (in) vmask |= 1u << sl;
    }

    const float* rbase = rgb + (size_t)b * Cc * HW;
    const float* tbase = tir + (size_t)b * Cc * HW;
    const uint32_t tiles_a = smem_u32(TILES);
    const uint32_t wb_a    = smem_u32(WB);
    const uint32_t wdw_a   = smem_u32(WDW);

    auto load_chunk = [&](int chunk, int bt) {
        const float* base = (chunk < 32 ? rbase : tbase) + (size_t)((chunk & 31) * CHK) * HW;
        uint32_t dst0 = tiles_a + bt * (TILEF * 4);
        #pragma unroll
        for (int sl = 0; sl < 4; sl++) {
            if (sl < 3 || tid < (NCP - 768)) {
                int in = (vmask >> sl) & 1;
                cpa16(dst0 + doff[sl], base + ofs[sl], in ? 16 : 0);
            }
        }
        if (tid < 128)
            cpa16(wb_a + (bt * 512 + tid * 4) * 4, g_wfrag + chunk * 512 + tid * 4, 16);
    };

    // stage B: thread = 8-px strip x 1 channel (warp w -> channel w of the chunk)
    // Also accumulates the tile's central-row sum for GAP (g_pooled).
    auto stageB = [&](int chunk, int bt, int xb) {
        const int py = l >> 2, pxx = (l & 3) * 8;
        const float* t0 = TILES + bt * TILEF + w * CHT + py * ROWF + pxx;
        const float* wd = WDW + chunk * (CHK * 12) + w * 12;
        float4 wa = *(const float4*)(wd);
        float4 wb = *(const float4*)(wd + 4);
        float2 wc = *(const float2*)(wd + 8);
        float o[8];
        #pragma unroll
        for (int j = 0; j < 8; j++) o[j] = wc.y;   // bias
        float csum = 0.f;
        #pragma unroll
        for (int r = 0; r < 3; r++) {
            const float* tr = t0 + r * ROWF;
            float v[10];
            v[0] = tr[3];
            float4 q1 = *(const float4*)(tr + 4);
            float4 q2 = *(const float4*)(tr + 8);
            v[9] = tr[12];
            v[1]=q1.x; v[2]=q1.y; v[3]=q1.z; v[4]=q1.w;
            v[5]=q2.x; v[6]=q2.y; v[7]=q2.z; v[8]=q2.w;
            float w0 = (r==0)?wa.x:(r==1)?wa.w:wb.z;
            float w1 = (r==0)?wa.y:(r==1)?wb.x:wb.w;
            float w2 = (r==0)?wa.z:(r==1)?wb.y:wc.x;
            #pragma unroll
            for (int j = 0; j < 8; j++)
                o[j] = fmaf(w0, v[j], fmaf(w1, v[j+1], fmaf(w2, v[j+2], o[j])));
            if (r == 1)
                csum = ((v[1]+v[2])+(v[3]+v[4])) + ((v[5]+v[6])+(v[7]+v[8]));
        }
        float* xp = XS + xb * (8 * CHP) + w * CHP + py * TW + pxx;
        *(float4*)xp       = make_float4(o[0], o[1], o[2], o[3]);
        *(float4*)(xp + 4) = make_float4(o[4], o[5], o[6], o[7]);
        #pragma unroll
        for (int oo = 16; oo; oo >>= 1) csum += __shfl_xor_sync(0xffffffffu, csum, oo);
        if (l == 0) atomicAdd(&g_pooled[b * C2 + chunk * CHK + w], csum);
    };

    float d[64];
    #pragma unroll
    for (int i = 0; i < 64; i++) d[i] = 0.f;

    // prologue: dw taps (once) + chunks 0,1,2 in flight
    for (int i = tid; i < C2 * 12; i += 256) {
        int c2 = i / 12, k = i - c2 * 12;
        const float* src = (k < 9) ? dww + c2 * 9 + k : dwb + c2;
        cpa4(wdw_a + i * 4, src, (k <= 9) ? 4 : 0);
    }
    load_chunk(0, 0); cpa_commit();
    load_chunk(1, 1); cpa_commit();
    load_chunk(2, 2); cpa_commit();
    cpa_wait2();                 // taps + chunk 0 resident
    __syncthreads();
    stageB(0, 0, 0);

    for (int chunk = 0; chunk < NCHUNK; chunk++) {
        if (chunk + 2 < NCHUNK) cpa_wait1();
        else                    cpa_wait0();
        __syncthreads();

        if (chunk + 3 < NCHUNK) { load_chunk(chunk + 3, (chunk + 3) & 3); cpa_commit(); }
        if (chunk + 1 < NCHUNK) stageB(chunk + 1, (chunk + 1) & 3, (chunk + 1) & 1);

        // ---- stage C: tensor GEMM on XS[chunk&1] with WB[chunk&3] ----
        const float* xbp = XS + (chunk & 1) * (8 * CHP);
        const float4* B4 = (const float4*)(WB + (chunk & 3) * 512);
        uint32_t a[2][4];
        const int c = l & 3, row = l >> 2;
        #pragma unroll
        for (int m = 0; m < 2; m++) {
            int px = w * 32 + m * 16 + row;
            a[m][0] = __float_as_uint(xbp[c * CHP + px]);
            a[m][1] = __float_as_uint(xbp[c * CHP + px + 8]);
            a[m][2] = __float_as_uint(xbp[(c + 4) * CHP + px]);
            a[m][3] = __float_as_uint(xbp[(c + 4) * CHP + px + 8]);
        }
        #pragma unroll
        for (int q = 0; q < 4; q++) {
            float4 B = B4[q * 32 + l];
            uint32_t b0a = __float_as_uint(B.x), b1a = __float_as_uint(B.y);
            uint32_t b0b = __float_as_uint(B.z), b1b = __float_as_uint(B.w);
            #pragma unroll
            for (int m = 0; m < 2; m++) {
                MMA_TF32(d + (m * 8 + 2 * q) * 4,     a[m], b0a, b1a);
                MMA_TF32(d + (m * 8 + 2 * q + 1) * 4, a[m], b0b, b1b);
            }
        }
    }

    // ---- Epilogue: bias + ReLU + folded p2, quad-reduce over hid lanes ----
    float4 oA[2], oB[2];
    #pragma unroll
    for (int m = 0; m < 2; m++) {
        oA[m] = make_float4(0.f, 0.f, 0.f, 0.f);
        oB[m] = make_float4(0.f, 0.f, 0.f, 0.f);
    }
    const float4* P2 = (const float4*)g_p2eff;
    #pragma unroll
    for (int t = 0; t < 8; t++) {
        int h0 = t * 8 + (l & 3) * 2;
        float4 e0 = P2[h0], e1 = P2[h0 + 1];
        float bb0 = p1b[h0], bb1 = p1b[h0 + 1];
        #pragma unroll
        for (int m = 0; m < 2; m++) {
            const float* dd = d + (m * 8 + t) * 4;
            float r0 = fmaxf(dd[0] + bb0, 0.f), r1 = fmaxf(dd[1] + bb1, 0.f);
            float r2 = fmaxf(dd[2] + bb0, 0.f), r3 = fmaxf(dd[3] + bb1, 0.f);
            oA[m].x += e0.x * r0 + e1.x * r1;  oA[m].y += e0.y * r0 + e1.y * r1;
            oA[m].z += e0.z * r0 + e1.z * r1;  oA[m].w += e0.w * r0 + e1.w * r1;
            oB[m].x += e0.x * r2 + e1.x * r3;  oB[m].y += e0.y * r2 + e1.y * r3;
            oB[m].z += e0.z * r2 + e1.z * r3;  oB[m].w += e0.w * r2 + e1.w * r3;
        }
    }
    #pragma unroll
    for (int m = 0; m < 2; m++) {
        #pragma unroll
        for (int o = 1; o <= 2; o <<= 1) {
            oA[m].x += __shfl_xor_sync(0xffffffffu, oA[m].x, o);
            oA[m].y += __shfl_xor_sync(0xffffffffu, oA[m].y, o);
            oA[m].z += __shfl_xor_sync(0xffffffffu, oA[m].z, o);
            oA[m].w += __shfl_xor_sync(0xffffffffu, oA[m].w, o);
            oB[m].x += __shfl_xor_sync(0xffffffffu, oB[m].x, o);
            oB[m].y += __shfl_xor_sync(0xffffffffu, oB[m].y, o);
            oB[m].z += __shfl_xor_sync(0xffffffffu, oB[m].z, o);
            oB[m].w += __shfl_xor_sync(0xffffffffu, oB[m].w, o);
        }
    }
    if ((l & 3) == 0) {
        float4 bo = make_float4(g_p2beff[0], g_p2beff[1], g_p2beff[2], g_p2beff[3]);
        int py = ty0 + w;
        size_t base = (size_t)b * HW + py * Ww + tx0;
        #pragma unroll
        for (int m = 0; m < 2; m++) {
            int cA = m * 16 + (l >> 2);
            float4 sA = make_float4(oA[m].x + bo.x, oA[m].y + bo.y, oA[m].z + bo.z, oA[m].w + bo.w);
            float4 sB = make_float4(oB[m].x + bo.x, oB[m].y + bo.y, oB[m].z + bo.z, oB[m].w + bo.w);
            ((float4*)g_off)[base + cA]     = sA;
            ((float4*)g_off)[base + cA + 8] = sB;
        }
    }
}

// ---------------- bilinear sample + mod (channel-split quarters) ----------------
__global__ __launch_bounds__(128, 12)
void sample_kernel(const float* __restrict__ rgb, const float* __restrict__ tir,
                   float* __restrict__ out) {
    int x = threadIdx.x;        // 128
    int y = blockIdx.x;         // 128
    int b = blockIdx.y;         // 8
    int quar = blockIdx.z;      // 0..3 -> channels [quar*64, quar*64+64)
    int c0 = quar * 64;
    __shared__ float smod[64];
    if (threadIdx.x < 64) smod[threadIdx.x] = g_mod[b * Cc + c0 + threadIdx.x];
    __syncthreads();
    int hw = y * Ww + x;
    int p = b * HW + hw;
    float4 off = ((const float4*)g_off)[p];

    float ixr = fminf(fmaxf((float)x + off.x, 0.f), 127.f);
    float iyr = fminf(fmaxf((float)y + off.y, 0.f), 127.f);
    float ixt = fminf(fmaxf((float)x + off.z, 0.f), 127.f);
    float iyt = fminf(fmaxf((float)y + off.w, 0.f), 127.f);

    float fx0r = floorf(ixr), fy0r = floorf(iyr);
    int x0r = (int)fx0r, y0r = (int)fy0r;
    int x1r = min(x0r + 1, 127), y1r = min(y0r + 1, 127);
    float wxr = ixr - fx0r, wyr = iyr - fy0r;
    float cxr = 1.f - wxr, cyr = 1.f - wyr;
    int i00r = y0r*Ww + x0r, i01r = y0r*Ww + x1r, i10r = y1r*Ww + x0r, i11r = y1r*Ww + x1r;

    float fx0t = floorf(ixt), fy0t = floorf(iyt);
    int x0t = (int)fx0t, y0t = (int)fy0t;
    int x1t = min(x0t + 1, 127), y1t = min(y0t + 1, 127);
    float wxt = ixt - fx0t, wyt = iyt - fy0t;
    float cxt = 1.f - wxt, cyt = 1.f - wyt;
    int i00t = y0t*Ww + x0t, i01t = y0t*Ww + x1t, i10t = y1t*Ww + x0t, i11t = y1t*Ww + x1t;

    const float* rb = rgb + ((size_t)b * Cc + c0) * HW;
    const float* tb = tir + ((size_t)b * Cc + c0) * HW;
    float* outR = out + ((size_t)b * Cc + c0) * HW + hw;
    float* outT = out + (size_t)Bn * Cc * HW + ((size_t)b * Cc + c0) * HW + hw;

    float qacc = 0.f;
    #pragma unroll 8
    for (int c = 0; c < 64; c++) {
        size_t co = (size_t)c * HW;
        float v00 = rb[co + i00r], v01 = rb[co + i01r];
        float v10 = rb[co + i10r], v11 = rb[co + i11r];
        float topr = v00 * cxr + v01 * wxr;
        float botr = v10 * cxr + v11 * wxr;
        float rv = (topr * cyr + botr * wyr) * smod[c];

        float u00 = tb[co + i00t], u01 = tb[co + i01t];
        float u10 = tb[co + i10t], u11 = tb[co + i11t];
        float topt = u00 * cxt + u01 * wxt;
        float bott = u10 * cxt + u11 * wxt;
        float tv = (topt * cyt + bott * wyt) * smod[c];

        outR[co] = rv;
        outT[co] = tv;
        qacc += fabsf(rv - tv);
    }
    g_qpart[quar][p] = qacc;
}

// ---------------- quality epilogue ----------------
__global__ void qual_kernel(float* __restrict__ out) {
    int p = blockIdx.x * 256 + threadIdx.x;
    float q = 1.f - ((g_qpart[0][p] + g_qpart[1][p]) + (g_qpart[2][p] + g_qpart[3][p]))
                    * (1.f / (float)Cc);
    out[(size_t)2 * Bn * Cc * HW + p] = 1.f / (1.f + expf(-q));
}

extern "C" void kernel_launch(void* const* d_in, const int* in_sizes, int n_in,
                              void* d_out, int out_size) {
    const float* rgb  = (const float*)d_in[0];
    const float* tir  = (const float*)d_in[1];
    const float* dw_w = (const float*)d_in[2];
    const float* dw_b = (const float*)d_in[3];
    const float* p1_w = (const float*)d_in[4];
    const float* p1_b = (const float*)d_in[5];
    const float* p2_w = (const float*)d_in[6];
    const float* p2_b = (const float*)d_in[7];
    const float* m1_w = (const float*)d_in[8];
    const float* m1_b = (const float*)d_in[9];
    const float* m2_w = (const float*)d_in[10];
    const float* m2_b = (const float*)d_in[11];
    float* out = (float*)d_out;

    cudaFuncSetAttribute(dwgemm_kernel, cudaFuncAttributeMaxDynamicSharedMemorySize, SMEM_BYTES);

    prep_kernel<<<129, 256>>>(p1_w, p2_w, p2_b);
    dwgemm_kernel<<<dim3(Ww / TW, Hh / TH, Bn), 256, SMEM_BYTES>>>(rgb, tir, dw_w, dw_b, p1_b);
    mod_kernel<<<Bn, 256>>>(m1_w, m1_b, m2_w, m2_b);
    sample_kernel<<<dim3(Hh, Bn, 4), 128>>>(rgb, tir, out);
    qual_kernel<<<BHW / 256, 256>>>(out);
}